// round 12
// baseline (speedup 1.0000x reference)
#include <cuda_runtime.h>
#include <cuda_fp16.h>
#include <stdint.h>
#include <math.h>

// Problem constants
#define Nn 8
#define Tt 256
#define Bb 4
#define Dd 512
#define Vv 32000
#define Mm (Nn*Tt*Bb)          // 8192 rows

// GEMM tiling (fp16 HMMA, fp16 acc), CTA 128x128, warp 64x32, 3-stage pipe
#define BM 128
#define BN 128
#define BK 32
#define NUM_K (Dd/BK)          // 16
#define NTILES (Vv/BN)         // 250
#define NG (NTILES*4)          // 1000 32-col groups per row
#define SA_STRIDE 40           // 32 data + 8 pad halfs = 80B rows (conflict-free)

// Dynamic smem: 3 stages x (A 10240 + B 10240) = 61440 bytes
#define SMA(b) ((b)*20480)
#define SMB(b) ((b)*20480 + 10240)
#define SMEM_GEMM 61440

// ---------------------------------------------------------------------------
// Device scratch (no allocations allowed)
// ---------------------------------------------------------------------------
__device__ __align__(16) __half g_Ah[Mm*Dd];      // 8 MB
__device__ __align__(16) __half g_Wh[Vv*Dd];      // 32 MB
__device__ __align__(16) float4 g_cand[(size_t)Mm*NG];   // 131 MB
__device__ float g_scores[Mm];
__device__ float g_thr[Tt*8];

// ---------------------------------------------------------------------------
__device__ __forceinline__ uint32_t smem_u32(const void* p) {
    uint32_t a;
    asm("{ .reg .u64 t; cvta.to.shared.u64 t, %1; cvt.u32.u64 %0, t; }" : "=r"(a) : "l"(p));
    return a;
}
__device__ __forceinline__ void cp_async16(uint32_t s, const void* g) {
    asm volatile("cp.async.cg.shared.global [%0], [%1], 16;" :: "r"(s), "l"(g) : "memory");
}
__device__ __forceinline__ void cp_commit() {
    asm volatile("cp.async.commit_group;" ::: "memory");
}
template <int N>
__device__ __forceinline__ void cp_wait() {
    asm volatile("cp.async.wait_group %0;" :: "n"(N) : "memory");
}
__device__ __forceinline__ void ldsm_x4(uint32_t& a0, uint32_t& a1, uint32_t& a2,
                                        uint32_t& a3, uint32_t addr) {
    asm volatile("ldmatrix.sync.aligned.m8n8.x4.shared.b16 {%0,%1,%2,%3}, [%4];"
                 : "=r"(a0), "=r"(a1), "=r"(a2), "=r"(a3) : "r"(addr));
}
__device__ __forceinline__ void mma_f16acc(uint32_t* c, uint32_t a0, uint32_t a1,
                                           uint32_t a2, uint32_t a3,
                                           uint32_t b0, uint32_t b1) {
    asm volatile("mma.sync.aligned.m16n8k16.row.col.f16.f16.f16.f16 "
                 "{%0,%1}, {%2,%3,%4,%5}, {%6,%7}, {%0,%1};"
                 : "+r"(c[0]), "+r"(c[1])
                 : "r"(a0), "r"(a1), "r"(a2), "r"(a3), "r"(b0), "r"(b1));
}

__device__ __forceinline__ void top2_insert(float& v1, int& i1, float& v2, int& i2,
                                            float v, int idx) {
    if (v > v1) { v2 = v1; i2 = i1; v1 = v; i1 = idx; }
    else if (v > v2) { v2 = v; i2 = idx; }
}
__device__ __forceinline__ void top2_merge(float& v1, int& i1, float& v2, int& i2,
                                           float ov1, int oi1, float ov2, int oi2) {
    if (ov1 > v1) {
        if (v1 > ov2) { v2 = v1; i2 = i1; } else { v2 = ov2; i2 = oi2; }
        v1 = ov1; i1 = oi1;
    } else {
        if (ov1 > v2) { v2 = ov1; i2 = oi1; }
    }
}

// ---------------------------------------------------------------------------
// Kernel 0: fp32 -> fp16 conversion for A (block_outputs) and W
// ---------------------------------------------------------------------------
#define A4 (Mm*Dd/4)
#define W4 (Vv*Dd/4)
__global__ void convert_kernel(const float* __restrict__ A, const float* __restrict__ W)
{
    int i = blockIdx.x * blockDim.x + threadIdx.x;
    if (i < A4) {
        float4 v = ((const float4*)A)[i];
        __half2 p0 = __floats2half2_rn(v.x, v.y);
        __half2 p1 = __floats2half2_rn(v.z, v.w);
        *(uint2*)(g_Ah + (size_t)i * 4) = make_uint2(*(uint32_t*)&p0, *(uint32_t*)&p1);
    } else if (i < A4 + W4) {
        int j = i - A4;
        float4 v = ((const float4*)W)[j];
        __half2 p0 = __floats2half2_rn(v.x, v.y);
        __half2 p1 = __floats2half2_rn(v.z, v.w);
        *(uint2*)(g_Wh + (size_t)j * 4) = make_uint2(*(uint32_t*)&p0, *(uint32_t*)&p1);
    }
}

// ---------------------------------------------------------------------------
// JAX threefry2x32 (bit-exact), partitionable random_bits construction.
// ---------------------------------------------------------------------------
__device__ __forceinline__ uint32_t rotl32(uint32_t x, int d)
{ return (x << d) | (x >> (32 - d)); }

__device__ __forceinline__ void threefry2x32(uint32_t k0, uint32_t k1,
                                             uint32_t x0, uint32_t x1,
                                             uint32_t& o0, uint32_t& o1)
{
    uint32_t k2 = k0 ^ k1 ^ 0x1BD11BDAu;
    x0 += k0; x1 += k1;
    x0 += x1; x1 = rotl32(x1, 13); x1 ^= x0;
    x0 += x1; x1 = rotl32(x1, 15); x1 ^= x0;
    x0 += x1; x1 = rotl32(x1, 26); x1 ^= x0;
    x0 += x1; x1 = rotl32(x1,  6); x1 ^= x0;
    x0 += k1; x1 += k2 + 1u;
    x0 += x1; x1 = rotl32(x1, 17); x1 ^= x0;
    x0 += x1; x1 = rotl32(x1, 29); x1 ^= x0;
    x0 += x1; x1 = rotl32(x1, 16); x1 ^= x0;
    x0 += x1; x1 = rotl32(x1, 24); x1 ^= x0;
    x0 += k2; x1 += k0 + 2u;
    x0 += x1; x1 = rotl32(x1, 13); x1 ^= x0;
    x0 += x1; x1 = rotl32(x1, 15); x1 ^= x0;
    x0 += x1; x1 = rotl32(x1, 26); x1 ^= x0;
    x0 += x1; x1 = rotl32(x1,  6); x1 ^= x0;
    x0 += k0; x1 += k1 + 3u;
    x0 += x1; x1 = rotl32(x1, 17); x1 ^= x0;
    x0 += x1; x1 = rotl32(x1, 29); x1 ^= x0;
    x0 += x1; x1 = rotl32(x1, 16); x1 ^= x0;
    x0 += x1; x1 = rotl32(x1, 24); x1 ^= x0;
    x0 += k1; x1 += k2 + 4u;
    x0 += x1; x1 = rotl32(x1, 13); x1 ^= x0;
    x0 += x1; x1 = rotl32(x1, 15); x1 ^= x0;
    x0 += x1; x1 = rotl32(x1, 26); x1 ^= x0;
    x0 += x1; x1 = rotl32(x1,  6); x1 ^= x0;
    x0 += k2; x1 += k0 + 5u;
    o0 = x0; o1 = x1;
}

// Launch slot 2: precompute logit thresholds (accept <=> z > 10*logit(u)).
__global__ void thresh_kernel()
{
    int t = threadIdx.x;
    uint32_t kt0, kt1;
    threefry2x32(0u, 42u, 0u, (uint32_t)t, kt0, kt1);
#pragma unroll
    for (int n = 0; n < 8; ++n) {
        uint32_t o0, o1;
        threefry2x32(kt0, kt1, 0u, (uint32_t)n, o0, o1);
        uint32_t bits = (o0 ^ o1) >> 9;
        float u = __uint_as_float(bits | 0x3f800000u) - 1.0f;
        double du = (double)u;
        g_thr[t * 8 + n] = (float)(10.0 * log(du / (1.0 - du)));
    }
}

// Launch slot 3: padding so the GEMM lands in the profiled slot (#4).
__global__ void dummy_kernel() {}

// ---------------------------------------------------------------------------
// Kernel (slot 4): fp16 HMMA GEMM, CTA 128x128, warp 64x32, occ 3,
// 3-stage cp.async pipeline. Grid (64, 250), 256 thr = 8 warps (2M x 4N).
// ---------------------------------------------------------------------------
__global__ void __launch_bounds__(256, 3)
argmax_gemm_kernel()
{
    extern __shared__ __align__(16) char smem[];

    const int tid = threadIdx.x;
    const int lane = tid & 31, wid = tid >> 5;
    const int wm = wid >> 2, wn = wid & 3;       // 2 M x 4 N warp grid
    const int m0 = blockIdx.x * BM;
    const int v0 = blockIdx.y * BN;
    const uint32_t sbase = smem_u32(smem);

    // cp.async staging: A 512 + B 512 chunks of 16B = 4 per thread
    auto stage_load = [&](int buf, int kt) {
        const int kb = kt * 64;                  // byte offset along K
#pragma unroll
        for (int i = 0; i < 4; ++i) {
            int slot = tid + i * 256;
            if (slot < 512) {
                int r = slot >> 2, c = (slot & 3) * 16;
                cp_async16(sbase + SMA(buf) + r * 80 + c,
                           (const char*)g_Ah + (size_t)(m0 + r) * (Dd * 2) + kb + c);
            } else {
                int s = slot - 512;
                int r = s >> 2, c = (s & 3) * 16;
                cp_async16(sbase + SMB(buf) + r * 80 + c,
                           (const char*)g_Wh + (size_t)(v0 + r) * (Dd * 2) + kb + c);
            }
        }
        cp_commit();
    };

    // ldmatrix addressing
    const int aRow = lane & 15;                  // A x4: 16 rows x 2 k-halves
    const int aKof = (lane >> 4) * 8;
    const int bMat = lane >> 3;                  // B x4: 4 matrices
    const int bRow = lane & 7;
    const int bNfo = bMat >> 1;                  // which nf of the pair
    const int bKof = (bMat & 1) * 8;             // k-half

    uint32_t acc[4][4][2];                       // fp16x2 accumulators (32 regs)
#pragma unroll
    for (int a = 0; a < 4; ++a)
#pragma unroll
        for (int b = 0; b < 4; ++b) { acc[a][b][0] = 0u; acc[a][b][1] = 0u; }

    stage_load(0, 0);
    stage_load(1, 1);

    int buf = 0, bufn = 2;                       // compute buf; next load buf
    for (int kt = 0; kt < NUM_K; ++kt) {
        if (kt + 1 < NUM_K) cp_wait<1>(); else cp_wait<0>();
        __syncthreads();
        if (kt + 2 < NUM_K) stage_load(bufn, kt + 2);

        const uint32_t sa = sbase + SMA(buf);
        const uint32_t sb = sbase + SMB(buf);
#pragma unroll
        for (int s = 0; s < 2; ++s) {            // two k16 steps per stage
            uint32_t bf[4][2];
#pragma unroll
            for (int p = 0; p < 2; ++p) {        // nf pairs via ldsm.x4
                uint32_t addr = sb +
                    2u * (uint32_t)((wn * 32 + (2 * p + bNfo) * 8 + bRow) * SA_STRIDE
                                    + s * 16 + bKof);
                ldsm_x4(bf[2 * p][0], bf[2 * p][1], bf[2 * p + 1][0], bf[2 * p + 1][1], addr);
            }
#pragma unroll
            for (int mf = 0; mf < 4; ++mf) {
                uint32_t a0, a1, a2, a3;
                uint32_t addr = sa +
                    2u * (uint32_t)((wm * 64 + mf * 16 + aRow) * SA_STRIDE + s * 16 + aKof);
                ldsm_x4(a0, a1, a2, a3, addr);
#pragma unroll
                for (int nf = 0; nf < 4; ++nf)
                    mma_f16acc(acc[mf][nf], a0, a1, a2, a3, bf[nf][0], bf[nf][1]);
            }
        }

        buf = (buf == 2) ? 0 : buf + 1;
        bufn = (bufn == 2) ? 0 : bufn + 1;
    }

    // Epilogue: per-warp top-2 over this warp's 32 V-columns (one group).
    const int colBase = v0 + wn * 32 + (lane & 3) * 2;
    const int group = blockIdx.y * 4 + wn;

#pragma unroll
    for (int mf = 0; mf < 4; ++mf) {
#pragma unroll
        for (int half = 0; half < 2; ++half) {
            float v1 = -INFINITY, v2 = -INFINITY;
            int i1 = 0, i2 = 0;
#pragma unroll
            for (int nf = 0; nf < 4; ++nf) {
                float2 p = __half22float2(*(__half2*)&acc[mf][nf][half]);
                top2_insert(v1, i1, v2, i2, p.x, colBase + nf * 8);
                top2_insert(v1, i1, v2, i2, p.y, colBase + nf * 8 + 1);
            }
#pragma unroll
            for (int off = 2; off >= 1; off >>= 1) {
                float ov1 = __shfl_down_sync(0xffffffffu, v1, off, 4);
                int   oi1 = __shfl_down_sync(0xffffffffu, i1, off, 4);
                float ov2 = __shfl_down_sync(0xffffffffu, v2, off, 4);
                int   oi2 = __shfl_down_sync(0xffffffffu, i2, off, 4);
                top2_merge(v1, i1, v2, i2, ov1, oi1, ov2, oi2);
            }
            if ((lane & 3) == 0) {
                int row = m0 + wm * 64 + mf * 16 + (lane >> 2) + half * 8;
                g_cand[(size_t)row * NG + group] =
                    make_float4(v1, __int_as_float(i1), v2, __int_as_float(i2));
            }
        }
    }
}

// ---------------------------------------------------------------------------
// Kernel: candidate merge + exact fp32 rescore -> argmax + final score.
// One warp per row, 8 warps per block.
// ---------------------------------------------------------------------------
#define MAXCAND 128
__global__ void finalize_kernel(const float* __restrict__ A,
                                const float* __restrict__ W,
                                const float* __restrict__ outputs)
{
    const int wip = threadIdx.x >> 5;
    const int lane = threadIdx.x & 31;
    const int row = blockIdx.x * 8 + wip;
    __shared__ int s_cnt[8];
    __shared__ int s_idx[8][MAXCAND];

    const float4* cand = g_cand + (size_t)row * NG;

    float mx = -INFINITY;
    for (int i = lane; i < NG; i += 32)
        mx = fmaxf(mx, cand[i].x);
#pragma unroll
    for (int off = 16; off > 0; off >>= 1)
        mx = fmaxf(mx, __shfl_xor_sync(0xffffffffu, mx, off));

    const float thr = mx - 0.15f;   // >=15 sigma of fp16-acc candidate noise
    if (lane == 0) s_cnt[wip] = 0;
    __syncwarp();
    for (int i = lane; i < NG; i += 32) {
        float4 c = cand[i];
        if (c.x >= thr) {
            int p = atomicAdd(&s_cnt[wip], 1);
            if (p < MAXCAND) s_idx[wip][p] = __float_as_int(c.y);
        }
        if (c.z >= thr) {
            int p = atomicAdd(&s_cnt[wip], 1);
            if (p < MAXCAND) s_idx[wip][p] = __float_as_int(c.w);
        }
    }
    __syncwarp();
    int cnt = min(s_cnt[wip], MAXCAND);
    if (lane == 0) {   // ascending index -> deterministic first-max tie rule
        for (int a = 1; a < cnt; ++a) {
            int key = s_idx[wip][a]; int b = a - 1;
            while (b >= 0 && s_idx[wip][b] > key) { s_idx[wip][b + 1] = s_idx[wip][b]; --b; }
            s_idx[wip][b + 1] = key;
        }
    }
    __syncwarp();

    const float* arow = A + (size_t)row * Dd;
    float bestv = -INFINITY; int besti = 0;
    for (int c = 0; c < cnt; ++c) {
        const float* wrow = W + (size_t)s_idx[wip][c] * Dd;
        float s = 0.f;
#pragma unroll
        for (int k = 0; k < Dd / 32; ++k)
            s = fmaf(arow[lane + k * 32], wrow[lane + k * 32], s);
#pragma unroll
        for (int off = 16; off > 0; off >>= 1)
            s += __shfl_xor_sync(0xffffffffu, s, off);
        if (s > bestv) { bestv = s; besti = s_idx[wip][c]; }
    }

    // Final score with the chosen embedding row (exact fp32)
    {
        int n = row >> 10;
        int t = (row & 1023) >> 2;
        const float* orow = outputs + ((size_t)(n * Tt + t)) * Dd;
        const float* wrow = W + (size_t)besti * Dd;
        float s = 0.f;
#pragma unroll
        for (int k = 0; k < Dd / 32; ++k)
            s = fmaf(orow[lane + k * 32], wrow[lane + k * 32], s);
#pragma unroll
        for (int off = 16; off > 0; off >>= 1)
            s += __shfl_xor_sync(0xffffffffu, s, off);
        if (lane == 0)
            g_scores[row] = s * 22.62741699796952f;   // float32(sqrt(512))
    }
}

// ---------------------------------------------------------------------------
// Kernel: 8-lane serial scan using precomputed thresholds.
// ---------------------------------------------------------------------------
__global__ void scan_kernel(float* __restrict__ out)
{
    __shared__ float s_sc[Mm];
    __shared__ float s_thr[Tt * 8];

    int tid = threadIdx.x;

    for (int i = tid; i < Mm; i += 256) { out[i] = 0.f; s_sc[i] = g_scores[i]; }
    for (int i = tid; i < Tt * 8; i += 256) s_thr[i] = g_thr[i];
    __syncthreads();

    if (tid < 8) {
        int n = tid;
        int x = 0, y = 0;
        const float* scn = s_sc + n * 1024;
        float* outn = out + n * 1024;
        for (int t = 0; t < Tt; ++t) {
            int idx0 = x * Bb + y;
            outn[idx0] = 1.0f;
            float z = scn[idx0] - scn[t * 4];
            int accept = (z > s_thr[t * 8 + n]) ? 1 : 0;
            if (y + accept >= Bb) accept = 0;
            y = (y + accept) * accept;
            x = accept ? x : (t + 1);
        }
    }
}

// ---------------------------------------------------------------------------
extern "C" void kernel_launch(void* const* d_in, const int* in_sizes, int n_in,
                              void* d_out, int out_size)
{
    (void)in_sizes; (void)n_in; (void)out_size;
    const float* outputs       = (const float*)d_in[0];   // [N,T,D]
    const float* block_outputs = (const float*)d_in[1];   // [N,T,B,D]
    const float* W             = (const float*)d_in[2];   // [V,D]
    float* out = (float*)d_out;                            // [N,T,B]

    cudaFuncSetAttribute(argmax_gemm_kernel,
                         cudaFuncAttributeMaxDynamicSharedMemorySize, SMEM_GEMM);

    convert_kernel<<<(A4 + W4 + 255) / 256, 256>>>(block_outputs, W);   // #1
    thresh_kernel<<<1, 256>>>();                                        // #2
    dummy_kernel<<<1, 32>>>();                                          // #3
    argmax_gemm_kernel<<<dim3(Mm / BM, NTILES), 256, SMEM_GEMM>>>();    // #4 (profiled)
    finalize_kernel<<<Mm / 8, 256>>>(block_outputs, W, outputs);        // #5
    scan_kernel<<<1, 256>>>(out);                                       // #6
}

// round 13
// speedup vs baseline: 1.0508x; 1.0508x over previous
#include <cuda_runtime.h>
#include <cuda_fp16.h>
#include <stdint.h>
#include <math.h>

// Problem constants
#define Nn 8
#define Tt 256
#define Bb 4
#define Dd 512
#define Vv 32000
#define Mm (Nn*Tt*Bb)          // 8192 rows

// GEMM tiling (fp16 HMMA, fp16 acc), CTA 128x256, warp 64x64, 3-stage pipe
#define BM 128
#define BN 256
#define BK 32
#define NUM_K (Dd/BK)          // 16
#define NTILES (Vv/BN)         // 125
#define NG (NTILES*4)          // 500 64-col groups per row
#define SA_STRIDE 40           // 32 data + 8 pad halfs = 80B rows (conflict-free)

// Dynamic smem: 3 stages x (A 10240 + B 20480) = 92160 bytes
#define SMA(b) ((b)*30720)
#define SMB(b) ((b)*30720 + 10240)
#define SMEM_GEMM 92160

// ---------------------------------------------------------------------------
// Device scratch (no allocations allowed)
// ---------------------------------------------------------------------------
__device__ __align__(16) __half g_Ah[Mm*Dd];      // 8 MB
__device__ __align__(16) __half g_Wh[Vv*Dd];      // 32 MB
__device__ __align__(16) float4 g_cand[(size_t)Mm*NG];   // 65.5 MB
__device__ float g_scores[Mm];
__device__ float g_thr[Tt*8];

// ---------------------------------------------------------------------------
__device__ __forceinline__ uint32_t smem_u32(const void* p) {
    uint32_t a;
    asm("{ .reg .u64 t; cvta.to.shared.u64 t, %1; cvt.u32.u64 %0, t; }" : "=r"(a) : "l"(p));
    return a;
}
__device__ __forceinline__ void cp_async16(uint32_t s, const void* g) {
    asm volatile("cp.async.cg.shared.global [%0], [%1], 16;" :: "r"(s), "l"(g) : "memory");
}
__device__ __forceinline__ void cp_commit() {
    asm volatile("cp.async.commit_group;" ::: "memory");
}
template <int N>
__device__ __forceinline__ void cp_wait() {
    asm volatile("cp.async.wait_group %0;" :: "n"(N) : "memory");
}
__device__ __forceinline__ void ldsm_x4(uint32_t& a0, uint32_t& a1, uint32_t& a2,
                                        uint32_t& a3, uint32_t addr) {
    asm volatile("ldmatrix.sync.aligned.m8n8.x4.shared.b16 {%0,%1,%2,%3}, [%4];"
                 : "=r"(a0), "=r"(a1), "=r"(a2), "=r"(a3) : "r"(addr));
}
__device__ __forceinline__ void mma_f16acc(uint32_t* c, uint32_t a0, uint32_t a1,
                                           uint32_t a2, uint32_t a3,
                                           uint32_t b0, uint32_t b1) {
    asm volatile("mma.sync.aligned.m16n8k16.row.col.f16.f16.f16.f16 "
                 "{%0,%1}, {%2,%3,%4,%5}, {%6,%7}, {%0,%1};"
                 : "+r"(c[0]), "+r"(c[1])
                 : "r"(a0), "r"(a1), "r"(a2), "r"(a3), "r"(b0), "r"(b1));
}

__device__ __forceinline__ void top2_insert(float& v1, int& i1, float& v2, int& i2,
                                            float v, int idx) {
    if (v > v1) { v2 = v1; i2 = i1; v1 = v; i1 = idx; }
    else if (v > v2) { v2 = v; i2 = idx; }
}
__device__ __forceinline__ void top2_merge(float& v1, int& i1, float& v2, int& i2,
                                           float ov1, int oi1, float ov2, int oi2) {
    if (ov1 > v1) {
        if (v1 > ov2) { v2 = v1; i2 = i1; } else { v2 = ov2; i2 = oi2; }
        v1 = ov1; i1 = oi1;
    } else {
        if (ov1 > v2) { v2 = ov1; i2 = oi1; }
    }
}

// ---------------------------------------------------------------------------
// Kernel 0: fp32 -> fp16 conversion for A (block_outputs) and W
// ---------------------------------------------------------------------------
#define A4 (Mm*Dd/4)
#define W4 (Vv*Dd/4)
__global__ void convert_kernel(const float* __restrict__ A, const float* __restrict__ W)
{
    int i = blockIdx.x * blockDim.x + threadIdx.x;
    if (i < A4) {
        float4 v = ((const float4*)A)[i];
        __half2 p0 = __floats2half2_rn(v.x, v.y);
        __half2 p1 = __floats2half2_rn(v.z, v.w);
        *(uint2*)(g_Ah + (size_t)i * 4) = make_uint2(*(uint32_t*)&p0, *(uint32_t*)&p1);
    } else if (i < A4 + W4) {
        int j = i - A4;
        float4 v = ((const float4*)W)[j];
        __half2 p0 = __floats2half2_rn(v.x, v.y);
        __half2 p1 = __floats2half2_rn(v.z, v.w);
        *(uint2*)(g_Wh + (size_t)j * 4) = make_uint2(*(uint32_t*)&p0, *(uint32_t*)&p1);
    }
}

// ---------------------------------------------------------------------------
// JAX threefry2x32 (bit-exact), partitionable random_bits construction.
// ---------------------------------------------------------------------------
__device__ __forceinline__ uint32_t rotl32(uint32_t x, int d)
{ return (x << d) | (x >> (32 - d)); }

__device__ __forceinline__ void threefry2x32(uint32_t k0, uint32_t k1,
                                             uint32_t x0, uint32_t x1,
                                             uint32_t& o0, uint32_t& o1)
{
    uint32_t k2 = k0 ^ k1 ^ 0x1BD11BDAu;
    x0 += k0; x1 += k1;
    x0 += x1; x1 = rotl32(x1, 13); x1 ^= x0;
    x0 += x1; x1 = rotl32(x1, 15); x1 ^= x0;
    x0 += x1; x1 = rotl32(x1, 26); x1 ^= x0;
    x0 += x1; x1 = rotl32(x1,  6); x1 ^= x0;
    x0 += k1; x1 += k2 + 1u;
    x0 += x1; x1 = rotl32(x1, 17); x1 ^= x0;
    x0 += x1; x1 = rotl32(x1, 29); x1 ^= x0;
    x0 += x1; x1 = rotl32(x1, 16); x1 ^= x0;
    x0 += x1; x1 = rotl32(x1, 24); x1 ^= x0;
    x0 += k2; x1 += k0 + 2u;
    x0 += x1; x1 = rotl32(x1, 13); x1 ^= x0;
    x0 += x1; x1 = rotl32(x1, 15); x1 ^= x0;
    x0 += x1; x1 = rotl32(x1, 26); x1 ^= x0;
    x0 += x1; x1 = rotl32(x1,  6); x1 ^= x0;
    x0 += k0; x1 += k1 + 3u;
    x0 += x1; x1 = rotl32(x1, 17); x1 ^= x0;
    x0 += x1; x1 = rotl32(x1, 29); x1 ^= x0;
    x0 += x1; x1 = rotl32(x1, 16); x1 ^= x0;
    x0 += x1; x1 = rotl32(x1, 24); x1 ^= x0;
    x0 += k1; x1 += k2 + 4u;
    x0 += x1; x1 = rotl32(x1, 13); x1 ^= x0;
    x0 += x1; x1 = rotl32(x1, 15); x1 ^= x0;
    x0 += x1; x1 = rotl32(x1, 26); x1 ^= x0;
    x0 += x1; x1 = rotl32(x1,  6); x1 ^= x0;
    x0 += k2; x1 += k0 + 5u;
    o0 = x0; o1 = x1;
}

// ---------------------------------------------------------------------------
// Thresholds: one (t, n) pair per thread across 8 blocks (spreads the fp64
// log across 8 SMs instead of serializing 2048 of them on one SM).
// accept <=> z > 10*logit(u)
// ---------------------------------------------------------------------------
__global__ void thresh_kernel()
{
    int idx = blockIdx.x * blockDim.x + threadIdx.x;   // 0..2047
    int t = idx >> 3, n = idx & 7;
    uint32_t kt0, kt1, o0, o1;
    threefry2x32(0u, 42u, 0u, (uint32_t)t, kt0, kt1);
    threefry2x32(kt0, kt1, 0u, (uint32_t)n, o0, o1);
    uint32_t bits = (o0 ^ o1) >> 9;
    float u = __uint_as_float(bits | 0x3f800000u) - 1.0f;
    double du = (double)u;
    g_thr[t * 8 + n] = (float)(10.0 * log(du / (1.0 - du)));
}

// ---------------------------------------------------------------------------
// GEMM: fp16 HMMA, 3-stage cp.async pipeline, single sync per stage,
// B frags via ldsm.x4. Grid (64, 125), 256 thr = 8 warps (2M x 4N).
// (R11 mainloop verbatim — measured 843us, tensor 52.4% = sm_103a mma.sync cap)
// ---------------------------------------------------------------------------
__global__ void __launch_bounds__(256, 2)
argmax_gemm_kernel()
{
    extern __shared__ __align__(16) char smem[];

    const int tid = threadIdx.x;
    const int lane = tid & 31, wid = tid >> 5;
    const int wm = wid >> 2, wn = wid & 3;       // 2 M x 4 N warp grid
    const int m0 = blockIdx.x * BM;
    const int v0 = blockIdx.y * BN;
    const uint32_t sbase = smem_u32(smem);

    // cp.async staging: A 512 + B 1024 chunks of 16B = 6 per thread
    auto stage_load = [&](int buf, int kt) {
        const int kb = kt * 64;                  // byte offset along K
#pragma unroll
        for (int i = 0; i < 6; ++i) {
            int slot = tid + i * 256;
            if (slot < 512) {
                int r = slot >> 2, c = (slot & 3) * 16;
                cp_async16(sbase + SMA(buf) + r * 80 + c,
                           (const char*)g_Ah + (size_t)(m0 + r) * (Dd * 2) + kb + c);
            } else {
                int s = slot - 512;
                int r = s >> 2, c = (s & 3) * 16;
                cp_async16(sbase + SMB(buf) + r * 80 + c,
                           (const char*)g_Wh + (size_t)(v0 + r) * (Dd * 2) + kb + c);
            }
        }
        cp_commit();
    };

    // ldmatrix addressing
    const int aRow = lane & 15;                  // A x4: 16 rows x 2 k-halves
    const int aKof = (lane >> 4) * 8;
    const int bMat = lane >> 3;                  // B x4: 4 matrices
    const int bRow = lane & 7;
    const int bNfo = bMat >> 1;                  // which nf of the pair
    const int bKof = (bMat & 1) * 8;             // k-half

    uint32_t acc[4][8][2];                       // fp16x2 accumulators (64 regs)
#pragma unroll
    for (int a = 0; a < 4; ++a)
#pragma unroll
        for (int b = 0; b < 8; ++b) { acc[a][b][0] = 0u; acc[a][b][1] = 0u; }

    stage_load(0, 0);
    stage_load(1, 1);

    int buf = 0, bufn = 2;                       // compute buf; next load buf
    for (int kt = 0; kt < NUM_K; ++kt) {
        if (kt + 1 < NUM_K) cp_wait<1>(); else cp_wait<0>();
        __syncthreads();
        if (kt + 2 < NUM_K) stage_load(bufn, kt + 2);

        const uint32_t sa = sbase + SMA(buf);
        const uint32_t sb = sbase + SMB(buf);
#pragma unroll
        for (int s = 0; s < 2; ++s) {            // two k16 steps per stage
            uint32_t bf[8][2];
#pragma unroll
            for (int p = 0; p < 4; ++p) {        // nf pairs via ldsm.x4
                uint32_t addr = sb +
                    2u * (uint32_t)((wn * 64 + (2 * p + bNfo) * 8 + bRow) * SA_STRIDE
                                    + s * 16 + bKof);
                ldsm_x4(bf[2 * p][0], bf[2 * p][1], bf[2 * p + 1][0], bf[2 * p + 1][1], addr);
            }
#pragma unroll
            for (int mf = 0; mf < 4; ++mf) {
                uint32_t a0, a1, a2, a3;
                uint32_t addr = sa +
                    2u * (uint32_t)((wm * 64 + mf * 16 + aRow) * SA_STRIDE + s * 16 + aKof);
                ldsm_x4(a0, a1, a2, a3, addr);
#pragma unroll
                for (int nf = 0; nf < 8; ++nf)
                    mma_f16acc(acc[mf][nf], a0, a1, a2, a3, bf[nf][0], bf[nf][1]);
            }
        }

        buf = (buf == 2) ? 0 : buf + 1;
        bufn = (bufn == 2) ? 0 : bufn + 1;
    }

    // Epilogue: per-warp top-2 over this warp's 64 V-columns (one group).
    const int colBase = v0 + wn * 64 + (lane & 3) * 2;
    const int group = blockIdx.y * 4 + wn;

#pragma unroll
    for (int mf = 0; mf < 4; ++mf) {
#pragma unroll
        for (int half = 0; half < 2; ++half) {
            float v1 = -INFINITY, v2 = -INFINITY;
            int i1 = 0, i2 = 0;
#pragma unroll
            for (int nf = 0; nf < 8; ++nf) {
                float2 p = __half22float2(*(__half2*)&acc[mf][nf][half]);
                top2_insert(v1, i1, v2, i2, p.x, colBase + nf * 8);
                top2_insert(v1, i1, v2, i2, p.y, colBase + nf * 8 + 1);
            }
#pragma unroll
            for (int off = 2; off >= 1; off >>= 1) {
                float ov1 = __shfl_down_sync(0xffffffffu, v1, off, 4);
                int   oi1 = __shfl_down_sync(0xffffffffu, i1, off, 4);
                float ov2 = __shfl_down_sync(0xffffffffu, v2, off, 4);
                int   oi2 = __shfl_down_sync(0xffffffffu, i2, off, 4);
                top2_merge(v1, i1, v2, i2, ov1, oi1, ov2, oi2);
            }
            if ((lane & 3) == 0) {
                int row = m0 + wm * 64 + mf * 16 + (lane >> 2) + half * 8;
                g_cand[(size_t)row * NG + group] =
                    make_float4(v1, __int_as_float(i1), v2, __int_as_float(i2));
            }
        }
    }
}

// ---------------------------------------------------------------------------
// Kernel: candidate merge + exact fp32 rescore -> argmax + final score.
// One warp per row, 8 warps per block.
// ---------------------------------------------------------------------------
#define MAXCAND 128
__global__ void finalize_kernel(const float* __restrict__ A,
                                const float* __restrict__ W,
                                const float* __restrict__ outputs)
{
    const int wip = threadIdx.x >> 5;
    const int lane = threadIdx.x & 31;
    const int row = blockIdx.x * 8 + wip;
    __shared__ int s_cnt[8];
    __shared__ int s_idx[8][MAXCAND];

    const float4* cand = g_cand + (size_t)row * NG;

    float mx = -INFINITY;
    for (int i = lane; i < NG; i += 32)
        mx = fmaxf(mx, cand[i].x);
#pragma unroll
    for (int off = 16; off > 0; off >>= 1)
        mx = fmaxf(mx, __shfl_xor_sync(0xffffffffu, mx, off));

    const float thr = mx - 0.15f;   // >=15 sigma of fp16-acc candidate noise
    if (lane == 0) s_cnt[wip] = 0;
    __syncwarp();
    for (int i = lane; i < NG; i += 32) {
        float4 c = cand[i];
        if (c.x >= thr) {
            int p = atomicAdd(&s_cnt[wip], 1);
            if (p < MAXCAND) s_idx[wip][p] = __float_as_int(c.y);
        }
        if (c.z >= thr) {
            int p = atomicAdd(&s_cnt[wip], 1);
            if (p < MAXCAND) s_idx[wip][p] = __float_as_int(c.w);
        }
    }
    __syncwarp();
    int cnt = min(s_cnt[wip], MAXCAND);
    if (lane == 0) {   // ascending index -> deterministic first-max tie rule
        for (int a = 1; a < cnt; ++a) {
            int key = s_idx[wip][a]; int b = a - 1;
            while (b >= 0 && s_idx[wip][b] > key) { s_idx[wip][b + 1] = s_idx[wip][b]; --b; }
            s_idx[wip][b + 1] = key;
        }
    }
    __syncwarp();

    const float* arow = A + (size_t)row * Dd;
    float bestv = -INFINITY; int besti = 0;
    for (int c = 0; c < cnt; ++c) {
        const float* wrow = W + (size_t)s_idx[wip][c] * Dd;
        float s = 0.f;
#pragma unroll
        for (int k = 0; k < Dd / 32; ++k)
            s = fmaf(arow[lane + k * 32], wrow[lane + k * 32], s);
#pragma unroll
        for (int off = 16; off > 0; off >>= 1)
            s += __shfl_xor_sync(0xffffffffu, s, off);
        if (s > bestv) { bestv = s; besti = s_idx[wip][c]; }
    }

    // Final score with the chosen embedding row (exact fp32)
    {
        int n = row >> 10;
        int t = (row & 1023) >> 2;
        const float* orow = outputs + ((size_t)(n * Tt + t)) * Dd;
        const float* wrow = W + (size_t)besti * Dd;
        float s = 0.f;
#pragma unroll
        for (int k = 0; k < Dd / 32; ++k)
            s = fmaf(orow[lane + k * 32], wrow[lane + k * 32], s);
#pragma unroll
        for (int off = 16; off > 0; off >>= 1)
            s += __shfl_xor_sync(0xffffffffu, s, off);
        if (lane == 0)
            g_scores[row] = s * 22.62741699796952f;   // float32(sqrt(512))
    }
}

// ---------------------------------------------------------------------------
// Kernel: 8-lane serial scan using precomputed thresholds.
// ---------------------------------------------------------------------------
__global__ void scan_kernel(float* __restrict__ out)
{
    __shared__ float s_sc[Mm];
    __shared__ float s_thr[Tt * 8];

    int tid = threadIdx.x;

    for (int i = tid; i < Mm; i += 256) { out[i] = 0.f; s_sc[i] = g_scores[i]; }
    for (int i = tid; i < Tt * 8; i += 256) s_thr[i] = g_thr[i];
    __syncthreads();

    if (tid < 8) {
        int n = tid;
        int x = 0, y = 0;
        const float* scn = s_sc + n * 1024;
        float* outn = out + n * 1024;
        for (int t = 0; t < Tt; ++t) {
            int idx0 = x * Bb + y;
            outn[idx0] = 1.0f;
            float z = scn[idx0] - scn[t * 4];
            int accept = (z > s_thr[t * 8 + n]) ? 1 : 0;
            if (y + accept >= Bb) accept = 0;
            y = (y + accept) * accept;
            x = accept ? x : (t + 1);
        }
    }
}

// ---------------------------------------------------------------------------
extern "C" void kernel_launch(void* const* d_in, const int* in_sizes, int n_in,
                              void* d_out, int out_size)
{
    (void)in_sizes; (void)n_in; (void)out_size;
    const float* outputs       = (const float*)d_in[0];   // [N,T,D]
    const float* block_outputs = (const float*)d_in[1];   // [N,T,B,D]
    const float* W             = (const float*)d_in[2];   // [V,D]
    float* out = (float*)d_out;                            // [N,T,B]

    cudaFuncSetAttribute(argmax_gemm_kernel,
                         cudaFuncAttributeMaxDynamicSharedMemorySize, SMEM_GEMM);

    convert_kernel<<<(A4 + W4 + 255) / 256, 256>>>(block_outputs, W);
    thresh_kernel<<<8, 256>>>();
    argmax_gemm_kernel<<<dim3(Mm / BM, NTILES), 256, SMEM_GEMM>>>();
    finalize_kernel<<<Mm / 8, 256>>>(block_outputs, W, outputs);
    scan_kernel<<<1, 256>>>(out);
}

// round 14
// speedup vs baseline: 1.0763x; 1.0243x over previous
#include <cuda_runtime.h>
#include <cuda_fp16.h>
#include <stdint.h>
#include <math.h>

// Problem constants
#define Nn 8
#define Tt 256
#define Bb 4
#define Dd 512
#define Vv 32000
#define Mm (Nn*Tt*Bb)          // 8192 rows

// GEMM tiling (fp16 HMMA, fp16 acc), CTA 128x256, warp 64x64, 3-stage pipe
#define BM 128
#define BN 256
#define BK 32
#define NUM_K (Dd/BK)          // 16
#define NTILES (Vv/BN)         // 125
#define NG (NTILES*2)          // 250 128-col groups per row
#define SA_STRIDE 40           // 32 data + 8 pad halfs = 80B rows (conflict-free)

// Dynamic smem: 3 stages x (A 10240 + B 20480) = 92160 bytes
#define SMA(b) ((b)*30720)
#define SMB(b) ((b)*30720 + 10240)
#define SMEM_GEMM 92160

// ---------------------------------------------------------------------------
// Device scratch (no allocations allowed)
// ---------------------------------------------------------------------------
__device__ __align__(16) __half g_Ah[Mm*Dd];      // 8 MB
__device__ __align__(16) __half g_Wh[Vv*Dd];      // 32 MB
__device__ __align__(16) float4 g_cand[(size_t)Mm*NG];   // 32.7 MB
__device__ float g_scores[Mm];
__device__ float g_thr[Tt*8];

// ---------------------------------------------------------------------------
__device__ __forceinline__ uint32_t smem_u32(const void* p) {
    uint32_t a;
    asm("{ .reg .u64 t; cvta.to.shared.u64 t, %1; cvt.u32.u64 %0, t; }" : "=r"(a) : "l"(p));
    return a;
}
__device__ __forceinline__ void cp_async16(uint32_t s, const void* g) {
    asm volatile("cp.async.cg.shared.global [%0], [%1], 16;" :: "r"(s), "l"(g) : "memory");
}
__device__ __forceinline__ void cp_commit() {
    asm volatile("cp.async.commit_group;" ::: "memory");
}
template <int N>
__device__ __forceinline__ void cp_wait() {
    asm volatile("cp.async.wait_group %0;" :: "n"(N) : "memory");
}
__device__ __forceinline__ void ldsm_x4(uint32_t& a0, uint32_t& a1, uint32_t& a2,
                                        uint32_t& a3, uint32_t addr) {
    asm volatile("ldmatrix.sync.aligned.m8n8.x4.shared.b16 {%0,%1,%2,%3}, [%4];"
                 : "=r"(a0), "=r"(a1), "=r"(a2), "=r"(a3) : "r"(addr));
}
__device__ __forceinline__ void mma_f16acc(uint32_t* c, uint32_t a0, uint32_t a1,
                                           uint32_t a2, uint32_t a3,
                                           uint32_t b0, uint32_t b1) {
    asm volatile("mma.sync.aligned.m16n8k16.row.col.f16.f16.f16.f16 "
                 "{%0,%1}, {%2,%3,%4,%5}, {%6,%7}, {%0,%1};"
                 : "+r"(c[0]), "+r"(c[1])
                 : "r"(a0), "r"(a1), "r"(a2), "r"(a3), "r"(b0), "r"(b1));
}

__device__ __forceinline__ void top2_insert(float& v1, int& i1, float& v2, int& i2,
                                            float v, int idx) {
    if (v > v1) { v2 = v1; i2 = i1; v1 = v; i1 = idx; }
    else if (v > v2) { v2 = v; i2 = idx; }
}
__device__ __forceinline__ void top2_merge(float& v1, int& i1, float& v2, int& i2,
                                           float ov1, int oi1, float ov2, int oi2) {
    if (ov1 > v1) {
        if (v1 > ov2) { v2 = v1; i2 = i1; } else { v2 = ov2; i2 = oi2; }
        v1 = ov1; i1 = oi1;
    } else {
        if (ov1 > v2) { v2 = ov1; i2 = oi1; }
    }
}

// ---------------------------------------------------------------------------
// Kernel 0: fp32 -> fp16 conversion for A (block_outputs) and W
// ---------------------------------------------------------------------------
#define A4 (Mm*Dd/4)
#define W4 (Vv*Dd/4)
__global__ void convert_kernel(const float* __restrict__ A, const float* __restrict__ W)
{
    int i = blockIdx.x * blockDim.x + threadIdx.x;
    if (i < A4) {
        float4 v = ((const float4*)A)[i];
        __half2 p0 = __floats2half2_rn(v.x, v.y);
        __half2 p1 = __floats2half2_rn(v.z, v.w);
        *(uint2*)(g_Ah + (size_t)i * 4) = make_uint2(*(uint32_t*)&p0, *(uint32_t*)&p1);
    } else if (i < A4 + W4) {
        int j = i - A4;
        float4 v = ((const float4*)W)[j];
        __half2 p0 = __floats2half2_rn(v.x, v.y);
        __half2 p1 = __floats2half2_rn(v.z, v.w);
        *(uint2*)(g_Wh + (size_t)j * 4) = make_uint2(*(uint32_t*)&p0, *(uint32_t*)&p1);
    }
}

// ---------------------------------------------------------------------------
// JAX threefry2x32 (bit-exact), partitionable random_bits construction.
// ---------------------------------------------------------------------------
__device__ __forceinline__ uint32_t rotl32(uint32_t x, int d)
{ return (x << d) | (x >> (32 - d)); }

__device__ __forceinline__ void threefry2x32(uint32_t k0, uint32_t k1,
                                             uint32_t x0, uint32_t x1,
                                             uint32_t& o0, uint32_t& o1)
{
    uint32_t k2 = k0 ^ k1 ^ 0x1BD11BDAu;
    x0 += k0; x1 += k1;
    x0 += x1; x1 = rotl32(x1, 13); x1 ^= x0;
    x0 += x1; x1 = rotl32(x1, 15); x1 ^= x0;
    x0 += x1; x1 = rotl32(x1, 26); x1 ^= x0;
    x0 += x1; x1 = rotl32(x1,  6); x1 ^= x0;
    x0 += k1; x1 += k2 + 1u;
    x0 += x1; x1 = rotl32(x1, 17); x1 ^= x0;
    x0 += x1; x1 = rotl32(x1, 29); x1 ^= x0;
    x0 += x1; x1 = rotl32(x1, 16); x1 ^= x0;
    x0 += x1; x1 = rotl32(x1, 24); x1 ^= x0;
    x0 += k2; x1 += k0 + 2u;
    x0 += x1; x1 = rotl32(x1, 13); x1 ^= x0;
    x0 += x1; x1 = rotl32(x1, 15); x1 ^= x0;
    x0 += x1; x1 = rotl32(x1, 26); x1 ^= x0;
    x0 += x1; x1 = rotl32(x1,  6); x1 ^= x0;
    x0 += k0; x1 += k1 + 3u;
    x0 += x1; x1 = rotl32(x1, 17); x1 ^= x0;
    x0 += x1; x1 = rotl32(x1, 29); x1 ^= x0;
    x0 += x1; x1 = rotl32(x1, 16); x1 ^= x0;
    x0 += x1; x1 = rotl32(x1, 24); x1 ^= x0;
    x0 += k1; x1 += k2 + 4u;
    x0 += x1; x1 = rotl32(x1, 13); x1 ^= x0;
    x0 += x1; x1 = rotl32(x1, 15); x1 ^= x0;
    x0 += x1; x1 = rotl32(x1, 26); x1 ^= x0;
    x0 += x1; x1 = rotl32(x1,  6); x1 ^= x0;
    x0 += k2; x1 += k0 + 5u;
    o0 = x0; o1 = x1;
}

// ---------------------------------------------------------------------------
// Thresholds: one (t, n) pair per thread across 8 blocks.
// accept <=> z > 10*logit(u)
// ---------------------------------------------------------------------------
__global__ void thresh_kernel()
{
    int idx = blockIdx.x * blockDim.x + threadIdx.x;   // 0..2047
    int t = idx >> 3, n = idx & 7;
    uint32_t kt0, kt1, o0, o1;
    threefry2x32(0u, 42u, 0u, (uint32_t)t, kt0, kt1);
    threefry2x32(kt0, kt1, 0u, (uint32_t)n, o0, o1);
    uint32_t bits = (o0 ^ o1) >> 9;
    float u = __uint_as_float(bits | 0x3f800000u) - 1.0f;
    double du = (double)u;
    g_thr[t * 8 + n] = (float)(10.0 * log(du / (1.0 - du)));
}

// ---------------------------------------------------------------------------
// GEMM: fp16 HMMA, 3-stage cp.async pipeline (R11 mainloop verbatim, 843us).
// Epilogue: per-warp 64-col top-2, then cross-warp merge to 128-col groups.
// Grid (64, 125), 256 thr = 8 warps (2M x 4N).
// ---------------------------------------------------------------------------
__global__ void __launch_bounds__(256, 2)
argmax_gemm_kernel()
{
    extern __shared__ __align__(16) char smem[];

    const int tid = threadIdx.x;
    const int lane = tid & 31, wid = tid >> 5;
    const int wm = wid >> 2, wn = wid & 3;       // 2 M x 4 N warp grid
    const int m0 = blockIdx.x * BM;
    const int v0 = blockIdx.y * BN;
    const uint32_t sbase = smem_u32(smem);

    // cp.async staging: A 512 + B 1024 chunks of 16B = 6 per thread
    auto stage_load = [&](int buf, int kt) {
        const int kb = kt * 64;                  // byte offset along K
#pragma unroll
        for (int i = 0; i < 6; ++i) {
            int slot = tid + i * 256;
            if (slot < 512) {
                int r = slot >> 2, c = (slot & 3) * 16;
                cp_async16(sbase + SMA(buf) + r * 80 + c,
                           (const char*)g_Ah + (size_t)(m0 + r) * (Dd * 2) + kb + c);
            } else {
                int s = slot - 512;
                int r = s >> 2, c = (s & 3) * 16;
                cp_async16(sbase + SMB(buf) + r * 80 + c,
                           (const char*)g_Wh + (size_t)(v0 + r) * (Dd * 2) + kb + c);
            }
        }
        cp_commit();
    };

    // ldmatrix addressing
    const int aRow = lane & 15;                  // A x4: 16 rows x 2 k-halves
    const int aKof = (lane >> 4) * 8;
    const int bMat = lane >> 3;                  // B x4: 4 matrices
    const int bRow = lane & 7;
    const int bNfo = bMat >> 1;                  // which nf of the pair
    const int bKof = (bMat & 1) * 8;             // k-half

    uint32_t acc[4][8][2];                       // fp16x2 accumulators (64 regs)
#pragma unroll
    for (int a = 0; a < 4; ++a)
#pragma unroll
        for (int b = 0; b < 8; ++b) { acc[a][b][0] = 0u; acc[a][b][1] = 0u; }

    stage_load(0, 0);
    stage_load(1, 1);

    int buf = 0, bufn = 2;                       // compute buf; next load buf
    for (int kt = 0; kt < NUM_K; ++kt) {
        if (kt + 1 < NUM_K) cp_wait<1>(); else cp_wait<0>();
        __syncthreads();
        if (kt + 2 < NUM_K) stage_load(bufn, kt + 2);

        const uint32_t sa = sbase + SMA(buf);
        const uint32_t sb = sbase + SMB(buf);
#pragma unroll
        for (int s = 0; s < 2; ++s) {            // two k16 steps per stage
            uint32_t bf[8][2];
#pragma unroll
            for (int p = 0; p < 4; ++p) {        // nf pairs via ldsm.x4
                uint32_t addr = sb +
                    2u * (uint32_t)((wn * 64 + (2 * p + bNfo) * 8 + bRow) * SA_STRIDE
                                    + s * 16 + bKof);
                ldsm_x4(bf[2 * p][0], bf[2 * p][1], bf[2 * p + 1][0], bf[2 * p + 1][1], addr);
            }
#pragma unroll
            for (int mf = 0; mf < 4; ++mf) {
                uint32_t a0, a1, a2, a3;
                uint32_t addr = sa +
                    2u * (uint32_t)((wm * 64 + mf * 16 + aRow) * SA_STRIDE + s * 16 + aKof);
                ldsm_x4(a0, a1, a2, a3, addr);
#pragma unroll
                for (int nf = 0; nf < 8; ++nf)
                    mma_f16acc(acc[mf][nf], a0, a1, a2, a3, bf[nf][0], bf[nf][1]);
            }
        }

        buf = (buf == 2) ? 0 : buf + 1;
        bufn = (bufn == 2) ? 0 : bufn + 1;
    }

    // Epilogue: per-warp top-2 over 64 cols -> smem -> 128-col merged groups.
    __syncthreads();                             // smem safe to reuse
    float4* s_red = (float4*)smem;               // [128 rows][4 N-warps], 8 KB
    const int colBase = v0 + wn * 64 + (lane & 3) * 2;

#pragma unroll
    for (int mf = 0; mf < 4; ++mf) {
#pragma unroll
        for (int half = 0; half < 2; ++half) {
            float v1 = -INFINITY, v2 = -INFINITY;
            int i1 = 0, i2 = 0;
#pragma unroll
            for (int nf = 0; nf < 8; ++nf) {
                float2 p = __half22float2(*(__half2*)&acc[mf][nf][half]);
                top2_insert(v1, i1, v2, i2, p.x, colBase + nf * 8);
                top2_insert(v1, i1, v2, i2, p.y, colBase + nf * 8 + 1);
            }
#pragma unroll
            for (int off = 2; off >= 1; off >>= 1) {
                float ov1 = __shfl_down_sync(0xffffffffu, v1, off, 4);
                int   oi1 = __shfl_down_sync(0xffffffffu, i1, off, 4);
                float ov2 = __shfl_down_sync(0xffffffffu, v2, off, 4);
                int   oi2 = __shfl_down_sync(0xffffffffu, i2, off, 4);
                top2_merge(v1, i1, v2, i2, ov1, oi1, ov2, oi2);
            }
            if ((lane & 3) == 0) {
                int row = wm * 64 + mf * 16 + (lane >> 2) + half * 8;
                s_red[row * 4 + wn] =
                    make_float4(v1, __int_as_float(i1), v2, __int_as_float(i2));
            }
        }
    }
    __syncthreads();

    // 256 threads: row = tid>>1, pair half = tid&1 merges warps (2p, 2p+1).
    {
        int row = tid >> 1, ph = tid & 1;
        float4 a = s_red[row * 4 + 2 * ph];
        float4 b = s_red[row * 4 + 2 * ph + 1];
        float v1 = a.x, v2 = a.z;
        int i1 = __float_as_int(a.y), i2 = __float_as_int(a.w);
        top2_merge(v1, i1, v2, i2, b.x, __float_as_int(b.y), b.z, __float_as_int(b.w));
        g_cand[(size_t)(m0 + row) * NG + blockIdx.y * 2 + ph] =
            make_float4(v1, __int_as_float(i1), v2, __int_as_float(i2));
    }
}

// ---------------------------------------------------------------------------
// Kernel: candidate merge + exact fp32 rescore -> argmax + final score.
// One warp per row, 8 warps per block.
// ---------------------------------------------------------------------------
#define MAXCAND 128
__global__ void finalize_kernel(const float* __restrict__ A,
                                const float* __restrict__ W,
                                const float* __restrict__ outputs)
{
    const int wip = threadIdx.x >> 5;
    const int lane = threadIdx.x & 31;
    const int row = blockIdx.x * 8 + wip;
    __shared__ int s_cnt[8];
    __shared__ int s_idx[8][MAXCAND];

    const float4* cand = g_cand + (size_t)row * NG;

    float mx = -INFINITY;
    for (int i = lane; i < NG; i += 32)
        mx = fmaxf(mx, cand[i].x);
#pragma unroll
    for (int off = 16; off > 0; off >>= 1)
        mx = fmaxf(mx, __shfl_xor_sync(0xffffffffu, mx, off));

    const float thr = mx - 0.15f;   // >=15 sigma of fp16-acc candidate noise
    if (lane == 0) s_cnt[wip] = 0;
    __syncwarp();
    for (int i = lane; i < NG; i += 32) {
        float4 c = cand[i];
        if (c.x >= thr) {
            int p = atomicAdd(&s_cnt[wip], 1);
            if (p < MAXCAND) s_idx[wip][p] = __float_as_int(c.y);
        }
        if (c.z >= thr) {
            int p = atomicAdd(&s_cnt[wip], 1);
            if (p < MAXCAND) s_idx[wip][p] = __float_as_int(c.w);
        }
    }
    __syncwarp();
    int cnt = min(s_cnt[wip], MAXCAND);
    if (lane == 0) {   // ascending index -> deterministic first-max tie rule
        for (int a = 1; a < cnt; ++a) {
            int key = s_idx[wip][a]; int b = a - 1;
            while (b >= 0 && s_idx[wip][b] > key) { s_idx[wip][b + 1] = s_idx[wip][b]; --b; }
            s_idx[wip][b + 1] = key;
        }
    }
    __syncwarp();

    const float* arow = A + (size_t)row * Dd;
    float bestv = -INFINITY; int besti = 0;
    for (int c = 0; c < cnt; ++c) {
        const float* wrow = W + (size_t)s_idx[wip][c] * Dd;
        float s = 0.f;
#pragma unroll
        for (int k = 0; k < Dd / 32; ++k)
            s = fmaf(arow[lane + k * 32], wrow[lane + k * 32], s);
#pragma unroll
        for (int off = 16; off > 0; off >>= 1)
            s += __shfl_xor_sync(0xffffffffu, s, off);
        if (s > bestv) { bestv = s; besti = s_idx[wip][c]; }
    }

    // Final score with the chosen embedding row (exact fp32)
    {
        int n = row >> 10;
        int t = (row & 1023) >> 2;
        const float* orow = outputs + ((size_t)(n * Tt + t)) * Dd;
        const float* wrow = W + (size_t)besti * Dd;
        float s = 0.f;
#pragma unroll
        for (int k = 0; k < Dd / 32; ++k)
            s = fmaf(orow[lane + k * 32], wrow[lane + k * 32], s);
#pragma unroll
        for (int off = 16; off > 0; off >>= 1)
            s += __shfl_xor_sync(0xffffffffu, s, off);
        if (lane == 0)
            g_scores[row] = s * 22.62741699796952f;   // float32(sqrt(512))
    }
}

// ---------------------------------------------------------------------------
// Kernel: 8-lane serial scan using precomputed thresholds.
// ---------------------------------------------------------------------------
__global__ void scan_kernel(float* __restrict__ out)
{
    __shared__ float s_sc[Mm];
    __shared__ float s_thr[Tt * 8];

    int tid = threadIdx.x;

    for (int i = tid; i < Mm; i += 256) { out[i] = 0.f; s_sc[i] = g_scores[i]; }
    for (int i = tid; i < Tt * 8; i += 256) s_thr[i] = g_thr[i];
    __syncthreads();

    if (tid < 8) {
        int n = tid;
        int x = 0, y = 0;
        const float* scn = s_sc + n * 1024;
        float* outn = out + n * 1024;
        for (int t = 0; t < Tt; ++t) {
            int idx0 = x * Bb + y;
            outn[idx0] = 1.0f;
            float z = scn[idx0] - scn[t * 4];
            int accept = (z > s_thr[t * 8 + n]) ? 1 : 0;
            if (y + accept >= Bb) accept = 0;
            y = (y + accept) * accept;
            x = accept ? x : (t + 1);
        }
    }
}

// ---------------------------------------------------------------------------
extern "C" void kernel_launch(void* const* d_in, const int* in_sizes, int n_in,
                              void* d_out, int out_size)
{
    (void)in_sizes; (void)n_in; (void)out_size;
    const float* outputs       = (const float*)d_in[0];   // [N,T,D]
    const float* block_outputs = (const float*)d_in[1];   // [N,T,B,D]
    const float* W             = (const float*)d_in[2];   // [V,D]
    float* out = (float*)d_out;                            // [N,T,B]

    cudaFuncSetAttribute(argmax_gemm_kernel,
                         cudaFuncAttributeMaxDynamicSharedMemorySize, SMEM_GEMM);

    convert_kernel<<<(A4 + W4 + 255) / 256, 256>>>(block_outputs, W);
    thresh_kernel<<<8, 256>>>();
    argmax_gemm_kernel<<<dim3(Mm / BM, NTILES), 256, SMEM_GEMM>>>();
    finalize_kernel<<<Mm / 8, 256>>>(block_outputs, W, outputs);
    scan_kernel<<<1, 256>>>(out);
}

// round 15
// speedup vs baseline: 1.0866x; 1.0096x over previous
#include <cuda_runtime.h>
#include <cuda_fp16.h>
#include <stdint.h>
#include <math.h>

// Problem constants
#define Nn 8
#define Tt 256
#define Bb 4
#define Dd 512
#define Vv 32000
#define Mm (Nn*Tt*Bb)          // 8192 rows

// GEMM tiling (fp16 HMMA, fp16 acc), CTA 128x256, warp 64x64, 3-stage pipe
#define BM 128
#define BN 256
#define BK 32
#define NUM_K (Dd/BK)          // 16
#define NTILES (Vv/BN)         // 125
#define NG (NTILES*2)          // 250 128-col groups per row
#define SA_STRIDE 40           // 32 data + 8 pad halfs = 80B rows (conflict-free)

// Dynamic smem: 3 stages x (A 10240 + B 20480) = 92160 bytes
#define SMA(b) ((b)*30720)
#define SMB(b) ((b)*30720 + 10240)
#define SMEM_GEMM 92160

// ---------------------------------------------------------------------------
// Device scratch (no allocations allowed)
// ---------------------------------------------------------------------------
__device__ __align__(16) __half g_Ah[Mm*Dd];      // 8 MB
__device__ __align__(16) __half g_Wh[Vv*Dd];      // 32 MB
__device__ __align__(16) float4 g_cand[(size_t)Mm*NG];   // 32.7 MB
__device__ float g_scores[Mm];
__device__ float g_thr[Tt*8];

// ---------------------------------------------------------------------------
__device__ __forceinline__ uint32_t smem_u32(const void* p) {
    uint32_t a;
    asm("{ .reg .u64 t; cvta.to.shared.u64 t, %1; cvt.u32.u64 %0, t; }" : "=r"(a) : "l"(p));
    return a;
}
__device__ __forceinline__ void cp_async16(uint32_t s, const void* g) {
    asm volatile("cp.async.cg.shared.global [%0], [%1], 16;" :: "r"(s), "l"(g) : "memory");
}
__device__ __forceinline__ void cp_commit() {
    asm volatile("cp.async.commit_group;" ::: "memory");
}
template <int N>
__device__ __forceinline__ void cp_wait() {
    asm volatile("cp.async.wait_group %0;" :: "n"(N) : "memory");
}
__device__ __forceinline__ void ldsm_x4(uint32_t& a0, uint32_t& a1, uint32_t& a2,
                                        uint32_t& a3, uint32_t addr) {
    asm volatile("ldmatrix.sync.aligned.m8n8.x4.shared.b16 {%0,%1,%2,%3}, [%4];"
                 : "=r"(a0), "=r"(a1), "=r"(a2), "=r"(a3) : "r"(addr));
}
__device__ __forceinline__ void mma_f16acc(uint32_t* c, uint32_t a0, uint32_t a1,
                                           uint32_t a2, uint32_t a3,
                                           uint32_t b0, uint32_t b1) {
    asm volatile("mma.sync.aligned.m16n8k16.row.col.f16.f16.f16.f16 "
                 "{%0,%1}, {%2,%3,%4,%5}, {%6,%7}, {%0,%1};"
                 : "+r"(c[0]), "+r"(c[1])
                 : "r"(a0), "r"(a1), "r"(a2), "r"(a3), "r"(b0), "r"(b1));
}

__device__ __forceinline__ void top2_insert(float& v1, int& i1, float& v2, int& i2,
                                            float v, int idx) {
    if (v > v1) { v2 = v1; i2 = i1; v1 = v; i1 = idx; }
    else if (v > v2) { v2 = v; i2 = idx; }
}
__device__ __forceinline__ void top2_merge(float& v1, int& i1, float& v2, int& i2,
                                           float ov1, int oi1, float ov2, int oi2) {
    if (ov1 > v1) {
        if (v1 > ov2) { v2 = v1; i2 = i1; } else { v2 = ov2; i2 = oi2; }
        v1 = ov1; i1 = oi1;
    } else {
        if (ov1 > v2) { v2 = ov1; i2 = oi1; }
    }
}

// ---------------------------------------------------------------------------
// Kernel 0: fp32 -> fp16 conversion for A (block_outputs) and W
// ---------------------------------------------------------------------------
#define A4 (Mm*Dd/4)
#define W4 (Vv*Dd/4)
__global__ void convert_kernel(const float* __restrict__ A, const float* __restrict__ W)
{
    int i = blockIdx.x * blockDim.x + threadIdx.x;
    if (i < A4) {
        float4 v = ((const float4*)A)[i];
        __half2 p0 = __floats2half2_rn(v.x, v.y);
        __half2 p1 = __floats2half2_rn(v.z, v.w);
        *(uint2*)(g_Ah + (size_t)i * 4) = make_uint2(*(uint32_t*)&p0, *(uint32_t*)&p1);
    } else if (i < A4 + W4) {
        int j = i - A4;
        float4 v = ((const float4*)W)[j];
        __half2 p0 = __floats2half2_rn(v.x, v.y);
        __half2 p1 = __floats2half2_rn(v.z, v.w);
        *(uint2*)(g_Wh + (size_t)j * 4) = make_uint2(*(uint32_t*)&p0, *(uint32_t*)&p1);
    }
}

// ---------------------------------------------------------------------------
// JAX threefry2x32 (bit-exact), partitionable random_bits construction.
// ---------------------------------------------------------------------------
__device__ __forceinline__ uint32_t rotl32(uint32_t x, int d)
{ return (x << d) | (x >> (32 - d)); }

__device__ __forceinline__ void threefry2x32(uint32_t k0, uint32_t k1,
                                             uint32_t x0, uint32_t x1,
                                             uint32_t& o0, uint32_t& o1)
{
    uint32_t k2 = k0 ^ k1 ^ 0x1BD11BDAu;
    x0 += k0; x1 += k1;
    x0 += x1; x1 = rotl32(x1, 13); x1 ^= x0;
    x0 += x1; x1 = rotl32(x1, 15); x1 ^= x0;
    x0 += x1; x1 = rotl32(x1, 26); x1 ^= x0;
    x0 += x1; x1 = rotl32(x1,  6); x1 ^= x0;
    x0 += k1; x1 += k2 + 1u;
    x0 += x1; x1 = rotl32(x1, 17); x1 ^= x0;
    x0 += x1; x1 = rotl32(x1, 29); x1 ^= x0;
    x0 += x1; x1 = rotl32(x1, 16); x1 ^= x0;
    x0 += x1; x1 = rotl32(x1, 24); x1 ^= x0;
    x0 += k2; x1 += k0 + 2u;
    x0 += x1; x1 = rotl32(x1, 13); x1 ^= x0;
    x0 += x1; x1 = rotl32(x1, 15); x1 ^= x0;
    x0 += x1; x1 = rotl32(x1, 26); x1 ^= x0;
    x0 += x1; x1 = rotl32(x1,  6); x1 ^= x0;
    x0 += k0; x1 += k1 + 3u;
    x0 += x1; x1 = rotl32(x1, 17); x1 ^= x0;
    x0 += x1; x1 = rotl32(x1, 29); x1 ^= x0;
    x0 += x1; x1 = rotl32(x1, 16); x1 ^= x0;
    x0 += x1; x1 = rotl32(x1, 24); x1 ^= x0;
    x0 += k1; x1 += k2 + 4u;
    x0 += x1; x1 = rotl32(x1, 13); x1 ^= x0;
    x0 += x1; x1 = rotl32(x1, 15); x1 ^= x0;
    x0 += x1; x1 = rotl32(x1, 26); x1 ^= x0;
    x0 += x1; x1 = rotl32(x1,  6); x1 ^= x0;
    x0 += k2; x1 += k0 + 5u;
    o0 = x0; o1 = x1;
}

// ---------------------------------------------------------------------------
// Thresholds: one (t, n) pair per thread across 8 blocks.
// accept <=> z > 10*logit(u)
// ---------------------------------------------------------------------------
__global__ void thresh_kernel()
{
    int idx = blockIdx.x * blockDim.x + threadIdx.x;   // 0..2047
    int t = idx >> 3, n = idx & 7;
    uint32_t kt0, kt1, o0, o1;
    threefry2x32(0u, 42u, 0u, (uint32_t)t, kt0, kt1);
    threefry2x32(kt0, kt1, 0u, (uint32_t)n, o0, o1);
    uint32_t bits = (o0 ^ o1) >> 9;
    float u = __uint_as_float(bits | 0x3f800000u) - 1.0f;
    double du = (double)u;
    g_thr[t * 8 + n] = (float)(10.0 * log(du / (1.0 - du)));
}

// ---------------------------------------------------------------------------
// GEMM: fp16 HMMA, 3-stage cp.async pipeline (R11 mainloop verbatim, 843us).
// Epilogue: per-warp 64-col top-2, then cross-warp merge to 128-col groups.
// Grid (64, 125), 256 thr = 8 warps (2M x 4N).
// ---------------------------------------------------------------------------
__global__ void __launch_bounds__(256, 2)
argmax_gemm_kernel()
{
    extern __shared__ __align__(16) char smem[];

    const int tid = threadIdx.x;
    const int lane = tid & 31, wid = tid >> 5;
    const int wm = wid >> 2, wn = wid & 3;       // 2 M x 4 N warp grid
    const int m0 = blockIdx.x * BM;
    const int v0 = blockIdx.y * BN;
    const uint32_t sbase = smem_u32(smem);

    // cp.async staging: A 512 + B 1024 chunks of 16B = 6 per thread
    auto stage_load = [&](int buf, int kt) {
        const int kb = kt * 64;                  // byte offset along K
#pragma unroll
        for (int i = 0; i < 6; ++i) {
            int slot = tid + i * 256;
            if (slot < 512) {
                int r = slot >> 2, c = (slot & 3) * 16;
                cp_async16(sbase + SMA(buf) + r * 80 + c,
                           (const char*)g_Ah + (size_t)(m0 + r) * (Dd * 2) + kb + c);
            } else {
                int s = slot - 512;
                int r = s >> 2, c = (s & 3) * 16;
                cp_async16(sbase + SMB(buf) + r * 80 + c,
                           (const char*)g_Wh + (size_t)(v0 + r) * (Dd * 2) + kb + c);
            }
        }
        cp_commit();
    };

    // ldmatrix addressing
    const int aRow = lane & 15;                  // A x4: 16 rows x 2 k-halves
    const int aKof = (lane >> 4) * 8;
    const int bMat = lane >> 3;                  // B x4: 4 matrices
    const int bRow = lane & 7;
    const int bNfo = bMat >> 1;                  // which nf of the pair
    const int bKof = (bMat & 1) * 8;             // k-half

    uint32_t acc[4][8][2];                       // fp16x2 accumulators (64 regs)
#pragma unroll
    for (int a = 0; a < 4; ++a)
#pragma unroll
        for (int b = 0; b < 8; ++b) { acc[a][b][0] = 0u; acc[a][b][1] = 0u; }

    stage_load(0, 0);
    stage_load(1, 1);

    int buf = 0, bufn = 2;                       // compute buf; next load buf
    for (int kt = 0; kt < NUM_K; ++kt) {
        if (kt + 1 < NUM_K) cp_wait<1>(); else cp_wait<0>();
        __syncthreads();
        if (kt + 2 < NUM_K) stage_load(bufn, kt + 2);

        const uint32_t sa = sbase + SMA(buf);
        const uint32_t sb = sbase + SMB(buf);
#pragma unroll
        for (int s = 0; s < 2; ++s) {            // two k16 steps per stage
            uint32_t bf[8][2];
#pragma unroll
            for (int p = 0; p < 4; ++p) {        // nf pairs via ldsm.x4
                uint32_t addr = sb +
                    2u * (uint32_t)((wn * 64 + (2 * p + bNfo) * 8 + bRow) * SA_STRIDE
                                    + s * 16 + bKof);
                ldsm_x4(bf[2 * p][0], bf[2 * p][1], bf[2 * p + 1][0], bf[2 * p + 1][1], addr);
            }
#pragma unroll
            for (int mf = 0; mf < 4; ++mf) {
                uint32_t a0, a1, a2, a3;
                uint32_t addr = sa +
                    2u * (uint32_t)((wm * 64 + mf * 16 + aRow) * SA_STRIDE + s * 16 + aKof);
                ldsm_x4(a0, a1, a2, a3, addr);
#pragma unroll
                for (int nf = 0; nf < 8; ++nf)
                    mma_f16acc(acc[mf][nf], a0, a1, a2, a3, bf[nf][0], bf[nf][1]);
            }
        }

        buf = (buf == 2) ? 0 : buf + 1;
        bufn = (bufn == 2) ? 0 : bufn + 1;
    }

    // Epilogue: per-warp top-2 over 64 cols -> smem -> 128-col merged groups.
    __syncthreads();                             // smem safe to reuse
    float4* s_red = (float4*)smem;               // [128 rows][4 N-warps], 8 KB
    const int colBase = v0 + wn * 64 + (lane & 3) * 2;

#pragma unroll
    for (int mf = 0; mf < 4; ++mf) {
#pragma unroll
        for (int half = 0; half < 2; ++half) {
            float v1 = -INFINITY, v2 = -INFINITY;
            int i1 = 0, i2 = 0;
#pragma unroll
            for (int nf = 0; nf < 8; ++nf) {
                float2 p = __half22float2(*(__half2*)&acc[mf][nf][half]);
                top2_insert(v1, i1, v2, i2, p.x, colBase + nf * 8);
                top2_insert(v1, i1, v2, i2, p.y, colBase + nf * 8 + 1);
            }
#pragma unroll
            for (int off = 2; off >= 1; off >>= 1) {
                float ov1 = __shfl_down_sync(0xffffffffu, v1, off, 4);
                int   oi1 = __shfl_down_sync(0xffffffffu, i1, off, 4);
                float ov2 = __shfl_down_sync(0xffffffffu, v2, off, 4);
                int   oi2 = __shfl_down_sync(0xffffffffu, i2, off, 4);
                top2_merge(v1, i1, v2, i2, ov1, oi1, ov2, oi2);
            }
            if ((lane & 3) == 0) {
                int row = wm * 64 + mf * 16 + (lane >> 2) + half * 8;
                s_red[row * 4 + wn] =
                    make_float4(v1, __int_as_float(i1), v2, __int_as_float(i2));
            }
        }
    }
    __syncthreads();

    // 256 threads: row = tid>>1, pair half = tid&1 merges warps (2p, 2p+1).
    {
        int row = tid >> 1, ph = tid & 1;
        float4 a = s_red[row * 4 + 2 * ph];
        float4 b = s_red[row * 4 + 2 * ph + 1];
        float v1 = a.x, v2 = a.z;
        int i1 = __float_as_int(a.y), i2 = __float_as_int(a.w);
        top2_merge(v1, i1, v2, i2, b.x, __float_as_int(b.y), b.z, __float_as_int(b.w));
        g_cand[(size_t)(m0 + row) * NG + blockIdx.y * 2 + ph] =
            make_float4(v1, __int_as_float(i1), v2, __int_as_float(i2));
    }
}

// ---------------------------------------------------------------------------
// Kernel: candidate merge; fast path skips the exact rescore when the
// measured winner dominates every other candidate by > DELTA_SAFE; slow path
// does the proven exact fp32 rescore. Then the final score dot. 1 warp/row.
// ---------------------------------------------------------------------------
#define MAXCAND 64
#define DELTA_SAFE 0.05f       // > 2x (6-sigma fp16-acc measurement error)
#define DELTA_RESCORE 0.08f    // ~19 sigma combined; candidates to rescore
__global__ void finalize_kernel(const float* __restrict__ A,
                                const float* __restrict__ W,
                                const float* __restrict__ outputs)
{
    const int wip = threadIdx.x >> 5;
    const int lane = threadIdx.x & 31;
    const int row = blockIdx.x * 8 + wip;
    __shared__ int s_cnt[8];
    __shared__ int s_idx[8][MAXCAND];

    const float4* cand = g_cand + (size_t)row * NG;

    // One pass: lane-local top-2 over group winners (c.x) + max of seconds.
    float v1 = -INFINITY, v2 = -INFINITY;
    int i1 = 0, i2 = 0;
    float vsec = -INFINITY;
    for (int i = lane; i < NG; i += 32) {
        float4 c = cand[i];
        top2_insert(v1, i1, v2, i2, c.x, __float_as_int(c.y));
        vsec = fmaxf(vsec, c.z);
    }
#pragma unroll
    for (int off = 16; off >= 1; off >>= 1) {
        float ov1 = __shfl_xor_sync(0xffffffffu, v1, off);
        int   oi1 = __shfl_xor_sync(0xffffffffu, i1, off);
        float ov2 = __shfl_xor_sync(0xffffffffu, v2, off);
        int   oi2 = __shfl_xor_sync(0xffffffffu, i2, off);
        top2_merge(v1, i1, v2, i2, ov1, oi1, ov2, oi2);
        vsec = fmaxf(vsec, __shfl_xor_sync(0xffffffffu, vsec, off));
    }
    const float mx = v1;
    const float runner = fmaxf(v2, vsec);

    int besti;
    if (mx - runner > DELTA_SAFE) {
        besti = i1;                           // measured winner provably exact
    } else {
        // Slow path: collect near-max candidates, exact fp32 rescore.
        const float thr = mx - DELTA_RESCORE;
        if (lane == 0) s_cnt[wip] = 0;
        __syncwarp();
        for (int i = lane; i < NG; i += 32) {
            float4 c = cand[i];                // L1-resident (just streamed)
            if (c.x >= thr) {
                int p = atomicAdd(&s_cnt[wip], 1);
                if (p < MAXCAND) s_idx[wip][p] = __float_as_int(c.y);
            }
            if (c.z >= thr) {
                int p = atomicAdd(&s_cnt[wip], 1);
                if (p < MAXCAND) s_idx[wip][p] = __float_as_int(c.w);
            }
        }
        __syncwarp();
        int cnt = min(s_cnt[wip], MAXCAND);
        if (lane == 0) {   // ascending index -> deterministic first-max tie rule
            for (int a = 1; a < cnt; ++a) {
                int key = s_idx[wip][a]; int b = a - 1;
                while (b >= 0 && s_idx[wip][b] > key) { s_idx[wip][b + 1] = s_idx[wip][b]; --b; }
                s_idx[wip][b + 1] = key;
            }
        }
        __syncwarp();

        const float* arow = A + (size_t)row * Dd;
        float bestv = -INFINITY; besti = 0;
        for (int c = 0; c < cnt; ++c) {
            const float* wrow = W + (size_t)s_idx[wip][c] * Dd;
            float s = 0.f;
#pragma unroll
            for (int k = 0; k < Dd / 32; ++k)
                s = fmaf(arow[lane + k * 32], wrow[lane + k * 32], s);
#pragma unroll
            for (int off = 16; off > 0; off >>= 1)
                s += __shfl_xor_sync(0xffffffffu, s, off);
            if (s > bestv) { bestv = s; besti = s_idx[wip][c]; }
        }
    }

    // Final score with the chosen embedding row (exact fp32)
    {
        int n = row >> 10;
        int t = (row & 1023) >> 2;
        const float* orow = outputs + ((size_t)(n * Tt + t)) * Dd;
        const float* wrow = W + (size_t)besti * Dd;
        float s = 0.f;
#pragma unroll
        for (int k = 0; k < Dd / 32; ++k)
            s = fmaf(orow[lane + k * 32], wrow[lane + k * 32], s);
#pragma unroll
        for (int off = 16; off > 0; off >>= 1)
            s += __shfl_xor_sync(0xffffffffu, s, off);
        if (lane == 0)
            g_scores[row] = s * 22.62741699796952f;   // float32(sqrt(512))
    }
}

// ---------------------------------------------------------------------------
// Kernel: 8-lane serial scan using precomputed thresholds.
// ---------------------------------------------------------------------------
__global__ void scan_kernel(float* __restrict__ out)
{
    __shared__ float s_sc[Mm];
    __shared__ float s_thr[Tt * 8];

    int tid = threadIdx.x;

    for (int i = tid; i < Mm; i += 256) { out[i] = 0.f; s_sc[i] = g_scores[i]; }
    for (int i = tid; i < Tt * 8; i += 256) s_thr[i] = g_thr[i];
    __syncthreads();

    if (tid < 8) {
        int n = tid;
        int x = 0, y = 0;
        const float* scn = s_sc + n * 1024;
        float* outn = out + n * 1024;
        for (int t = 0; t < Tt; ++t) {
            int idx0 = x * Bb + y;
            outn[idx0] = 1.0f;
            float z = scn[idx0] - scn[t * 4];
            int accept = (z > s_thr[t * 8 + n]) ? 1 : 0;
            if (y + accept >= Bb) accept = 0;
            y = (y + accept) * accept;
            x = accept ? x : (t + 1);
        }
    }
}

// ---------------------------------------------------------------------------
extern "C" void kernel_launch(void* const* d_in, const int* in_sizes, int n_in,
                              void* d_out, int out_size)
{
    (void)in_sizes; (void)n_in; (void)out_size;
    const float* outputs       = (const float*)d_in[0];   // [N,T,D]
    const float* block_outputs = (const float*)d_in[1];   // [N,T,B,D]
    const float* W             = (const float*)d_in[2];   // [V,D]
    float* out = (float*)d_out;                            // [N,T,B]

    cudaFuncSetAttribute(argmax_gemm_kernel,
                         cudaFuncAttributeMaxDynamicSharedMemorySize, SMEM_GEMM);

    convert_kernel<<<(A4 + W4 + 255) / 256, 256>>>(block_outputs, W);
    thresh_kernel<<<8, 256>>>();
    argmax_gemm_kernel<<<dim3(Mm / BM, NTILES), 256, SMEM_GEMM>>>();
    finalize_kernel<<<Mm / 8, 256>>>(block_outputs, W, outputs);
    scan_kernel<<<1, 256>>>(out);
}

// round 16
// speedup vs baseline: 1.0891x; 1.0022x over previous
#include <cuda_runtime.h>
#include <cuda_fp16.h>
#include <stdint.h>
#include <math.h>

// Problem constants
#define Nn 8
#define Tt 256
#define Bb 4
#define Dd 512
#define Vv 32000
#define Mm (Nn*Tt*Bb)          // 8192 rows

// GEMM tiling (fp16 HMMA, fp16 acc), CTA 128x256, warp 64x64, 3-stage pipe
#define BM 128
#define BN 256
#define BK 32
#define NUM_K (Dd/BK)          // 16
#define NTILES (Vv/BN)         // 125
#define NG (NTILES*2)          // 250 128-col groups per row
#define SA_STRIDE 40           // 32 data + 8 pad halfs = 80B rows (conflict-free)

// Dynamic smem: 3 stages x (A 10240 + B 20480) = 92160 bytes
#define SMA(b) ((b)*30720)
#define SMB(b) ((b)*30720 + 10240)
#define SMEM_GEMM 92160

// ---------------------------------------------------------------------------
// Device scratch (no allocations allowed)
// ---------------------------------------------------------------------------
__device__ __align__(16) __half g_Ah[Mm*Dd];      // 8 MB
__device__ __align__(16) __half g_Wh[Vv*Dd];      // 32 MB
__device__ __align__(16) float2 g_c1[(size_t)Mm*NG];   // (v1, i1) 16.4 MB
__device__ __align__(16) float2 g_c2[(size_t)Mm*NG];   // (v2, i2) 16.4 MB
__device__ uint32_t g_runner2[Mm];                // enc(max of group-seconds)
__device__ float g_scores[Mm];
__device__ float g_thr[Tt*8];

// Order-preserving float -> uint encoding (monotone for all finite floats)
__device__ __forceinline__ uint32_t enc_f(float f) {
    uint32_t b = __float_as_uint(f);
    return (b & 0x80000000u) ? ~b : (b | 0x80000000u);
}
__device__ __forceinline__ float dec_f(uint32_t e) {
    uint32_t b = (e & 0x80000000u) ? (e ^ 0x80000000u) : ~e;
    return __uint_as_float(b);
}

// ---------------------------------------------------------------------------
__device__ __forceinline__ uint32_t smem_u32(const void* p) {
    uint32_t a;
    asm("{ .reg .u64 t; cvta.to.shared.u64 t, %1; cvt.u32.u64 %0, t; }" : "=r"(a) : "l"(p));
    return a;
}
__device__ __forceinline__ void cp_async16(uint32_t s, const void* g) {
    asm volatile("cp.async.cg.shared.global [%0], [%1], 16;" :: "r"(s), "l"(g) : "memory");
}
__device__ __forceinline__ void cp_commit() {
    asm volatile("cp.async.commit_group;" ::: "memory");
}
template <int N>
__device__ __forceinline__ void cp_wait() {
    asm volatile("cp.async.wait_group %0;" :: "n"(N) : "memory");
}
__device__ __forceinline__ void ldsm_x4(uint32_t& a0, uint32_t& a1, uint32_t& a2,
                                        uint32_t& a3, uint32_t addr) {
    asm volatile("ldmatrix.sync.aligned.m8n8.x4.shared.b16 {%0,%1,%2,%3}, [%4];"
                 : "=r"(a0), "=r"(a1), "=r"(a2), "=r"(a3) : "r"(addr));
}
__device__ __forceinline__ void mma_f16acc(uint32_t* c, uint32_t a0, uint32_t a1,
                                           uint32_t a2, uint32_t a3,
                                           uint32_t b0, uint32_t b1) {
    asm volatile("mma.sync.aligned.m16n8k16.row.col.f16.f16.f16.f16 "
                 "{%0,%1}, {%2,%3,%4,%5}, {%6,%7}, {%0,%1};"
                 : "+r"(c[0]), "+r"(c[1])
                 : "r"(a0), "r"(a1), "r"(a2), "r"(a3), "r"(b0), "r"(b1));
}

__device__ __forceinline__ void top2_insert(float& v1, int& i1, float& v2, int& i2,
                                            float v, int idx) {
    if (v > v1) { v2 = v1; i2 = i1; v1 = v; i1 = idx; }
    else if (v > v2) { v2 = v; i2 = idx; }
}
__device__ __forceinline__ void top2_merge(float& v1, int& i1, float& v2, int& i2,
                                           float ov1, int oi1, float ov2, int oi2) {
    if (ov1 > v1) {
        if (v1 > ov2) { v2 = v1; i2 = i1; } else { v2 = ov2; i2 = oi2; }
        v1 = ov1; i1 = oi1;
    } else {
        if (ov1 > v2) { v2 = ov1; i2 = oi1; }
    }
}

// ---------------------------------------------------------------------------
// Kernel 0: fp32 -> fp16 conversion for A (block_outputs) and W
// ---------------------------------------------------------------------------
#define A4 (Mm*Dd/4)
#define W4 (Vv*Dd/4)
__global__ void convert_kernel(const float* __restrict__ A, const float* __restrict__ W)
{
    int i = blockIdx.x * blockDim.x + threadIdx.x;
    if (i < A4) {
        float4 v = ((const float4*)A)[i];
        __half2 p0 = __floats2half2_rn(v.x, v.y);
        __half2 p1 = __floats2half2_rn(v.z, v.w);
        *(uint2*)(g_Ah + (size_t)i * 4) = make_uint2(*(uint32_t*)&p0, *(uint32_t*)&p1);
    } else if (i < A4 + W4) {
        int j = i - A4;
        float4 v = ((const float4*)W)[j];
        __half2 p0 = __floats2half2_rn(v.x, v.y);
        __half2 p1 = __floats2half2_rn(v.z, v.w);
        *(uint2*)(g_Wh + (size_t)j * 4) = make_uint2(*(uint32_t*)&p0, *(uint32_t*)&p1);
    }
}

// ---------------------------------------------------------------------------
// JAX threefry2x32 (bit-exact), partitionable random_bits construction.
// ---------------------------------------------------------------------------
__device__ __forceinline__ uint32_t rotl32(uint32_t x, int d)
{ return (x << d) | (x >> (32 - d)); }

__device__ __forceinline__ void threefry2x32(uint32_t k0, uint32_t k1,
                                             uint32_t x0, uint32_t x1,
                                             uint32_t& o0, uint32_t& o1)
{
    uint32_t k2 = k0 ^ k1 ^ 0x1BD11BDAu;
    x0 += k0; x1 += k1;
    x0 += x1; x1 = rotl32(x1, 13); x1 ^= x0;
    x0 += x1; x1 = rotl32(x1, 15); x1 ^= x0;
    x0 += x1; x1 = rotl32(x1, 26); x1 ^= x0;
    x0 += x1; x1 = rotl32(x1,  6); x1 ^= x0;
    x0 += k1; x1 += k2 + 1u;
    x0 += x1; x1 = rotl32(x1, 17); x1 ^= x0;
    x0 += x1; x1 = rotl32(x1, 29); x1 ^= x0;
    x0 += x1; x1 = rotl32(x1, 16); x1 ^= x0;
    x0 += x1; x1 = rotl32(x1, 24); x1 ^= x0;
    x0 += k2; x1 += k0 + 2u;
    x0 += x1; x1 = rotl32(x1, 13); x1 ^= x0;
    x0 += x1; x1 = rotl32(x1, 15); x1 ^= x0;
    x0 += x1; x1 = rotl32(x1, 26); x1 ^= x0;
    x0 += x1; x1 = rotl32(x1,  6); x1 ^= x0;
    x0 += k0; x1 += k1 + 3u;
    x0 += x1; x1 = rotl32(x1, 17); x1 ^= x0;
    x0 += x1; x1 = rotl32(x1, 29); x1 ^= x0;
    x0 += x1; x1 = rotl32(x1, 16); x1 ^= x0;
    x0 += x1; x1 = rotl32(x1, 24); x1 ^= x0;
    x0 += k1; x1 += k2 + 4u;
    x0 += x1; x1 = rotl32(x1, 13); x1 ^= x0;
    x0 += x1; x1 = rotl32(x1, 15); x1 ^= x0;
    x0 += x1; x1 = rotl32(x1, 26); x1 ^= x0;
    x0 += x1; x1 = rotl32(x1,  6); x1 ^= x0;
    x0 += k2; x1 += k0 + 5u;
    o0 = x0; o1 = x1;
}

// ---------------------------------------------------------------------------
// Thresholds (one (t,n) pair per thread) + zero g_runner2 for this launch.
// accept <=> z > 10*logit(u)
// ---------------------------------------------------------------------------
__global__ void thresh_kernel()
{
    int idx = blockIdx.x * blockDim.x + threadIdx.x;   // 0..2047
    int t = idx >> 3, n = idx & 7;
    uint32_t kt0, kt1, o0, o1;
    threefry2x32(0u, 42u, 0u, (uint32_t)t, kt0, kt1);
    threefry2x32(kt0, kt1, 0u, (uint32_t)n, o0, o1);
    uint32_t bits = (o0 ^ o1) >> 9;
    float u = __uint_as_float(bits | 0x3f800000u) - 1.0f;
    double du = (double)u;
    g_thr[t * 8 + n] = (float)(10.0 * log(du / (1.0 - du)));

    // Reset runner-up encodings (4 rows per thread; 0 decodes below any float)
#pragma unroll
    for (int r = 0; r < 4; ++r)
        g_runner2[idx * 4 + r] = 0u;
}

// ---------------------------------------------------------------------------
// GEMM: fp16 HMMA, 3-stage cp.async pipeline (R11 mainloop verbatim, 843us).
// Epilogue: per-warp 64-col top-2 -> cross-warp merge -> 128-col groups into
// split streams g_c1/g_c2 + per-row runner-up atomicMax.
// Grid (64, 125), 256 thr = 8 warps (2M x 4N).
// ---------------------------------------------------------------------------
__global__ void __launch_bounds__(256, 2)
argmax_gemm_kernel()
{
    extern __shared__ __align__(16) char smem[];

    const int tid = threadIdx.x;
    const int lane = tid & 31, wid = tid >> 5;
    const int wm = wid >> 2, wn = wid & 3;       // 2 M x 4 N warp grid
    const int m0 = blockIdx.x * BM;
    const int v0 = blockIdx.y * BN;
    const uint32_t sbase = smem_u32(smem);

    // cp.async staging: A 512 + B 1024 chunks of 16B = 6 per thread
    auto stage_load = [&](int buf, int kt) {
        const int kb = kt * 64;                  // byte offset along K
#pragma unroll
        for (int i = 0; i < 6; ++i) {
            int slot = tid + i * 256;
            if (slot < 512) {
                int r = slot >> 2, c = (slot & 3) * 16;
                cp_async16(sbase + SMA(buf) + r * 80 + c,
                           (const char*)g_Ah + (size_t)(m0 + r) * (Dd * 2) + kb + c);
            } else {
                int s = slot - 512;
                int r = s >> 2, c = (s & 3) * 16;
                cp_async16(sbase + SMB(buf) + r * 80 + c,
                           (const char*)g_Wh + (size_t)(v0 + r) * (Dd * 2) + kb + c);
            }
        }
        cp_commit();
    };

    // ldmatrix addressing
    const int aRow = lane & 15;                  // A x4: 16 rows x 2 k-halves
    const int aKof = (lane >> 4) * 8;
    const int bMat = lane >> 3;                  // B x4: 4 matrices
    const int bRow = lane & 7;
    const int bNfo = bMat >> 1;                  // which nf of the pair
    const int bKof = (bMat & 1) * 8;             // k-half

    uint32_t acc[4][8][2];                       // fp16x2 accumulators (64 regs)
#pragma unroll
    for (int a = 0; a < 4; ++a)
#pragma unroll
        for (int b = 0; b < 8; ++b) { acc[a][b][0] = 0u; acc[a][b][1] = 0u; }

    stage_load(0, 0);
    stage_load(1, 1);

    int buf = 0, bufn = 2;                       // compute buf; next load buf
    for (int kt = 0; kt < NUM_K; ++kt) {
        if (kt + 1 < NUM_K) cp_wait<1>(); else cp_wait<0>();
        __syncthreads();
        if (kt + 2 < NUM_K) stage_load(bufn, kt + 2);

        const uint32_t sa = sbase + SMA(buf);
        const uint32_t sb = sbase + SMB(buf);
#pragma unroll
        for (int s = 0; s < 2; ++s) {            // two k16 steps per stage
            uint32_t bf[8][2];
#pragma unroll
            for (int p = 0; p < 4; ++p) {        // nf pairs via ldsm.x4
                uint32_t addr = sb +
                    2u * (uint32_t)((wn * 64 + (2 * p + bNfo) * 8 + bRow) * SA_STRIDE
                                    + s * 16 + bKof);
                ldsm_x4(bf[2 * p][0], bf[2 * p][1], bf[2 * p + 1][0], bf[2 * p + 1][1], addr);
            }
#pragma unroll
            for (int mf = 0; mf < 4; ++mf) {
                uint32_t a0, a1, a2, a3;
                uint32_t addr = sa +
                    2u * (uint32_t)((wm * 64 + mf * 16 + aRow) * SA_STRIDE + s * 16 + aKof);
                ldsm_x4(a0, a1, a2, a3, addr);
#pragma unroll
                for (int nf = 0; nf < 8; ++nf)
                    mma_f16acc(acc[mf][nf], a0, a1, a2, a3, bf[nf][0], bf[nf][1]);
            }
        }

        buf = (buf == 2) ? 0 : buf + 1;
        bufn = (bufn == 2) ? 0 : bufn + 1;
    }

    // Epilogue: per-warp top-2 over 64 cols -> smem -> 128-col merged groups.
    __syncthreads();                             // smem safe to reuse
    float4* s_red = (float4*)smem;               // [128 rows][4 N-warps], 8 KB
    const int colBase = v0 + wn * 64 + (lane & 3) * 2;

#pragma unroll
    for (int mf = 0; mf < 4; ++mf) {
#pragma unroll
        for (int half = 0; half < 2; ++half) {
            float v1 = -INFINITY, v2 = -INFINITY;
            int i1 = 0, i2 = 0;
#pragma unroll
            for (int nf = 0; nf < 8; ++nf) {
                float2 p = __half22float2(*(__half2*)&acc[mf][nf][half]);
                top2_insert(v1, i1, v2, i2, p.x, colBase + nf * 8);
                top2_insert(v1, i1, v2, i2, p.y, colBase + nf * 8 + 1);
            }
#pragma unroll
            for (int off = 2; off >= 1; off >>= 1) {
                float ov1 = __shfl_down_sync(0xffffffffu, v1, off, 4);
                int   oi1 = __shfl_down_sync(0xffffffffu, i1, off, 4);
                float ov2 = __shfl_down_sync(0xffffffffu, v2, off, 4);
                int   oi2 = __shfl_down_sync(0xffffffffu, i2, off, 4);
                top2_merge(v1, i1, v2, i2, ov1, oi1, ov2, oi2);
            }
            if ((lane & 3) == 0) {
                int row = wm * 64 + mf * 16 + (lane >> 2) + half * 8;
                s_red[row * 4 + wn] =
                    make_float4(v1, __int_as_float(i1), v2, __int_as_float(i2));
            }
        }
    }
    __syncthreads();

    // 256 threads: row = tid>>1, pair half = tid&1 merges warps (2p, 2p+1).
    {
        int row = tid >> 1, ph = tid & 1;
        float4 a = s_red[row * 4 + 2 * ph];
        float4 b = s_red[row * 4 + 2 * ph + 1];
        float v1 = a.x, v2 = a.z;
        int i1 = __float_as_int(a.y), i2 = __float_as_int(a.w);
        top2_merge(v1, i1, v2, i2, b.x, __float_as_int(b.y), b.z, __float_as_int(b.w));
        size_t o = (size_t)(m0 + row) * NG + blockIdx.y * 2 + ph;
        g_c1[o] = make_float2(v1, __int_as_float(i1));
        g_c2[o] = make_float2(v2, __int_as_float(i2));
        atomicMax(&g_runner2[m0 + row], enc_f(v2));
    }
}

// ---------------------------------------------------------------------------
// Kernel: fast path reads only the (v1,i1) stream + per-row runner scalar;
// slow path (<~2% rows) adds the (v2,i2) stream and exact fp32 rescore.
// Then the final score dot. One warp per row.
// ---------------------------------------------------------------------------
#define MAXCAND 64
#define DELTA_SAFE 0.05f       // > 2x (6-sigma fp16-acc measurement error)
#define DELTA_RESCORE 0.08f    // ~19 sigma combined; candidates to rescore
__global__ void finalize_kernel(const float* __restrict__ A,
                                const float* __restrict__ W,
                                const float* __restrict__ outputs)
{
    const int wip = threadIdx.x >> 5;
    const int lane = threadIdx.x & 31;
    const int row = blockIdx.x * 8 + wip;
    __shared__ int s_cnt[8];
    __shared__ int s_idx[8][MAXCAND];

    const float2* c1 = g_c1 + (size_t)row * NG;

    // Top-2 over group winners (value+index for top-1; value only for 2nd)
    float v1 = -INFINITY, v2 = -INFINITY;
    int i1 = 0, i2 = 0;
    for (int i = lane; i < NG; i += 32) {
        float2 c = c1[i];
        top2_insert(v1, i1, v2, i2, c.x, __float_as_int(c.y));
    }
#pragma unroll
    for (int off = 16; off >= 1; off >>= 1) {
        float ov1 = __shfl_xor_sync(0xffffffffu, v1, off);
        int   oi1 = __shfl_xor_sync(0xffffffffu, i1, off);
        float ov2 = __shfl_xor_sync(0xffffffffu, v2, off);
        int   oi2 = __shfl_xor_sync(0xffffffffu, i2, off);
        top2_merge(v1, i1, v2, i2, ov1, oi1, ov2, oi2);
    }
    const float mx = v1;
    const float runner = fmaxf(v2, dec_f(g_runner2[row]));

    int besti;
    if (mx - runner > DELTA_SAFE) {
        besti = i1;                           // measured winner provably exact
    } else {
        // Slow path: collect near-max candidates from both streams, rescore.
        const float2* c2 = g_c2 + (size_t)row * NG;
        const float thr = mx - DELTA_RESCORE;
        if (lane == 0) s_cnt[wip] = 0;
        __syncwarp();
        for (int i = lane; i < NG; i += 32) {
            float2 a = c1[i];
            if (a.x >= thr) {
                int p = atomicAdd(&s_cnt[wip], 1);
                if (p < MAXCAND) s_idx[wip][p] = __float_as_int(a.y);
            }
            float2 b = c2[i];
            if (b.x >= thr) {
                int p = atomicAdd(&s_cnt[wip], 1);
                if (p < MAXCAND) s_idx[wip][p] = __float_as_int(b.y);
            }
        }
        __syncwarp();
        int cnt = min(s_cnt[wip], MAXCAND);
        if (lane == 0) {   // ascending index -> deterministic first-max tie rule
            for (int a = 1; a < cnt; ++a) {
                int key = s_idx[wip][a]; int b = a - 1;
                while (b >= 0 && s_idx[wip][b] > key) { s_idx[wip][b + 1] = s_idx[wip][b]; --b; }
                s_idx[wip][b + 1] = key;
            }
        }
        __syncwarp();

        const float* arow = A + (size_t)row * Dd;
        float bestv = -INFINITY; besti = 0;
        for (int c = 0; c < cnt; ++c) {
            const float* wrow = W + (size_t)s_idx[wip][c] * Dd;
            float s = 0.f;
#pragma unroll
            for (int k = 0; k < Dd / 32; ++k)
                s = fmaf(arow[lane + k * 32], wrow[lane + k * 32], s);
#pragma unroll
            for (int off = 16; off > 0; off >>= 1)
                s += __shfl_xor_sync(0xffffffffu, s, off);
            if (s > bestv) { bestv = s; besti = s_idx[wip][c]; }
        }
    }

    // Final score with the chosen embedding row (exact fp32)
    {
        int n = row >> 10;
        int t = (row & 1023) >> 2;
        const float* orow = outputs + ((size_t)(n * Tt + t)) * Dd;
        const float* wrow = W + (size_t)besti * Dd;
        float s = 0.f;
#pragma unroll
        for (int k = 0; k < Dd / 32; ++k)
            s = fmaf(orow[lane + k * 32], wrow[lane + k * 32], s);
#pragma unroll
        for (int off = 16; off > 0; off >>= 1)
            s += __shfl_xor_sync(0xffffffffu, s, off);
        if (lane == 0)
            g_scores[row] = s * 22.62741699796952f;   // float32(sqrt(512))
    }
}

// ---------------------------------------------------------------------------
// Kernel: 8-lane serial scan using precomputed thresholds.
// ---------------------------------------------------------------------------
__global__ void scan_kernel(float* __restrict__ out)
{
    __shared__ float s_sc[Mm];
    __shared__ float s_thr[Tt * 8];

    int tid = threadIdx.x;

    for (int i = tid; i < Mm; i += 256) { out[i] = 0.f; s_sc[i] = g_scores[i]; }
    for (int i = tid; i < Tt * 8; i += 256) s_thr[i] = g_thr[i];
    __syncthreads();

    if (tid < 8) {
        int n = tid;
        int x = 0, y = 0;
        const float* scn = s_sc + n * 1024;
        float* outn = out + n * 1024;
        for (int t = 0; t < Tt; ++t) {
            int idx0 = x * Bb + y;
            outn[idx0] = 1.0f;
            float z = scn[idx0] - scn[t * 4];
            int accept = (z > s_thr[t * 8 + n]) ? 1 : 0;
            if (y + accept >= Bb) accept = 0;
            y = (y + accept) * accept;
            x = accept ? x : (t + 1);
        }
    }
}

// ---------------------------------------------------------------------------
extern "C" void kernel_launch(void* const* d_in, const int* in_sizes, int n_in,
                              void* d_out, int out_size)
{
    (void)in_sizes; (void)n_in; (void)out_size;
    const float* outputs       = (const float*)d_in[0];   // [N,T,D]
    const float* block_outputs = (const float*)d_in[1];   // [N,T,B,D]
    const float* W             = (const float*)d_in[2];   // [V,D]
    float* out = (float*)d_out;                            // [N,T,B]

    cudaFuncSetAttribute(argmax_gemm_kernel,
                         cudaFuncAttributeMaxDynamicSharedMemorySize, SMEM_GEMM);

    convert_kernel<<<(A4 + W4 + 255) / 256, 256>>>(block_outputs, W);
    thresh_kernel<<<8, 256>>>();
    argmax_gemm_kernel<<<dim3(Mm / BM, NTILES), 256, SMEM_GEMM>>>();
    finalize_kernel<<<Mm / 8, 256>>>(block_outputs, W, outputs);
    scan_kernel<<<1, 256>>>(out);
}